// round 1
// baseline (speedup 1.0000x reference)
#include <cuda_runtime.h>
#include <cstdint>
#include <math.h>

#define BB 8
#define LL 512
#define DD 4096
#define HH 8
#define FF 16384
#define AA 512   // per-head dim == L

// ---------------- scratch (device globals: allocation-free) ----------------
__device__ float g_xn [BB*LL*DD];          // 64MB  ln output (reused for ln2)
__device__ float g_q  [HH*BB*LL*AA];       // 64MB  (H, B*L, A)
__device__ float g_k  [HH*BB*LL*AA];       // 64MB
__device__ float g_v  [HH*BB*LL*AA];       // 64MB
__device__ float g_s  [HH*BB*LL*LL];       // 64MB  (H, B, L, L)
__device__ float g_att[BB*LL*DD];          // 64MB  concat-head attention (B*L, D)
__device__ float g_x1 [BB*LL*DD];          // 64MB  residual after fc
__device__ float g_h  [BB*LL*FF];          // 256MB MLP hidden

// ---------------- helpers ----------------
__device__ __forceinline__ uint32_t f2tf(float f) {
    uint32_t r;
    asm("cvt.rna.tf32.f32 %0, %1;" : "=r"(r) : "f"(f));
    return r;
}

__device__ __forceinline__ float gelu_exact(float x) {
    return 0.5f * x * (1.0f + erff(x * 0.7071067811865475f));
}

// ---------------- layernorm: one block per row of 4096 ----------------
__global__ void ln_kernel(const float* __restrict__ x,
                          const float* __restrict__ g,
                          const float* __restrict__ b,
                          float* __restrict__ out)
{
    int row = blockIdx.x;
    const float4* xr = (const float4*)(x + (size_t)row * DD);
    __shared__ float red[256];
    float4 vals[4];
    float s = 0.f;
#pragma unroll
    for (int it = 0; it < 4; ++it) {
        float4 v = xr[threadIdx.x + it * 256];
        vals[it] = v;
        s += v.x + v.y + v.z + v.w;
    }
    red[threadIdx.x] = s; __syncthreads();
    for (int st = 128; st > 0; st >>= 1) {
        if (threadIdx.x < st) red[threadIdx.x] += red[threadIdx.x + st];
        __syncthreads();
    }
    float mean = red[0] * (1.f / DD);
    __syncthreads();
    float vs = 0.f;
#pragma unroll
    for (int it = 0; it < 4; ++it) {
        float4 v = vals[it];
        float dx = v.x - mean, dy = v.y - mean, dz = v.z - mean, dw = v.w - mean;
        vs += dx*dx + dy*dy + dz*dz + dw*dw;
    }
    red[threadIdx.x] = vs; __syncthreads();
    for (int st = 128; st > 0; st >>= 1) {
        if (threadIdx.x < st) red[threadIdx.x] += red[threadIdx.x + st];
        __syncthreads();
    }
    float rstd = rsqrtf(red[0] * (1.f / DD) + 1e-5f);
    float4* o = (float4*)(out + (size_t)row * DD);
#pragma unroll
    for (int it = 0; it < 4; ++it) {
        int c = (threadIdx.x + it * 256) * 4;
        float4 v = vals[it];
        float4 gg = *(const float4*)(g + c);
        float4 bb = *(const float4*)(b + c);
        float4 r;
        r.x = (v.x - mean) * rstd * gg.x + bb.x;
        r.y = (v.y - mean) * rstd * gg.y + bb.y;
        r.z = (v.z - mean) * rstd * gg.z + bb.z;
        r.w = (v.w - mean) * rstd * gg.w + bb.w;
        o[threadIdx.x + it * 256] = r;
    }
}

// ---------------- generic tf32 mma.sync GEMM ----------------
// C[M,N] = A[M,K] @ op(B) (+ bias) (+ gelu) (+ residual)
// A row-major lda=K. NN: B row-major (K,N) ldb=N. BT: B row-major (N,K) ldb=K (computes A@B^T).
// EPI: 0 = none, 1 = bias + residual, 2 = bias + gelu
// 128x128x32 block tile, 256 threads (8 warps of 64x32), m16n8k8.tf32
template<int EPI, bool BT, int LDBS>
__global__ void __launch_bounds__(256, 2)
gemm_tf32(const float* __restrict__ A, const float* __restrict__ B,
          float* __restrict__ C, const float* __restrict__ bias,
          const float* __restrict__ res,
          int M, int N, int K,
          long long sA, long long sB, long long sC)
{
    constexpr int LDAS = 36;
    __shared__ uint32_t As[128 * LDAS];
    __shared__ uint32_t Bs[32 * LDBS];

    int z = blockIdx.z;
    A += (long long)z * sA;
    B += (long long)z * sB;
    C += (long long)z * sC;

    int m0 = blockIdx.y * 128, n0 = blockIdx.x * 128;
    int tid = threadIdx.x;
    int warp = tid >> 5, lane = tid & 31;
    int wm = (warp >> 2) * 64, wn = (warp & 3) * 32;
    int gid = lane >> 2, tig = lane & 3;

    float acc[4][4][4];
#pragma unroll
    for (int a = 0; a < 4; ++a)
#pragma unroll
        for (int b = 0; b < 4; ++b)
#pragma unroll
            for (int c = 0; c < 4; ++c) acc[a][b][c] = 0.f;

    for (int kt = 0; kt < K; kt += 32) {
        // load A tile 128x32 (tf32 into smem, [m][k])
#pragma unroll
        for (int it = 0; it < 4; ++it) {
            int idx = tid + it * 256;
            int rm = idx >> 3, c4 = idx & 7;
            float4 v = *(const float4*)(A + (size_t)(m0 + rm) * K + kt + c4 * 4);
            uint32_t* dst = &As[rm * LDAS + c4 * 4];
            dst[0] = f2tf(v.x); dst[1] = f2tf(v.y); dst[2] = f2tf(v.z); dst[3] = f2tf(v.w);
        }
        if (!BT) {
            // B tile 32x128 from (K,N) row-major, [k][n]
#pragma unroll
            for (int it = 0; it < 4; ++it) {
                int idx = tid + it * 256;
                int rk = idx >> 5, c4 = idx & 31;
                float4 v = *(const float4*)(B + (size_t)(kt + rk) * N + n0 + c4 * 4);
                uint32_t* dst = &Bs[rk * LDBS + c4 * 4];
                dst[0] = f2tf(v.x); dst[1] = f2tf(v.y); dst[2] = f2tf(v.z); dst[3] = f2tf(v.w);
            }
        } else {
            // B tile from (N,K) row-major: transpose into [k][n]
#pragma unroll
            for (int it = 0; it < 4; ++it) {
                int idx = tid + it * 256;
                int rn = idx >> 3, c4 = idx & 7;
                float4 v = *(const float4*)(B + (size_t)(n0 + rn) * K + kt + c4 * 4);
                Bs[(c4 * 4 + 0) * LDBS + rn] = f2tf(v.x);
                Bs[(c4 * 4 + 1) * LDBS + rn] = f2tf(v.y);
                Bs[(c4 * 4 + 2) * LDBS + rn] = f2tf(v.z);
                Bs[(c4 * 4 + 3) * LDBS + rn] = f2tf(v.w);
            }
        }
        __syncthreads();

#pragma unroll
        for (int ks = 0; ks < 4; ++ks) {
            uint32_t af[4][4], bf[4][2];
#pragma unroll
            for (int mf = 0; mf < 4; ++mf) {
                const uint32_t* p = &As[(wm + mf * 16 + gid) * LDAS + ks * 8 + tig];
                af[mf][0] = p[0];
                af[mf][1] = p[8 * LDAS];
                af[mf][2] = p[4];
                af[mf][3] = p[8 * LDAS + 4];
            }
#pragma unroll
            for (int nf = 0; nf < 4; ++nf) {
                const uint32_t* p = &Bs[(ks * 8 + tig) * LDBS + wn + nf * 8 + gid];
                bf[nf][0] = p[0];
                bf[nf][1] = p[4 * LDBS];
            }
#pragma unroll
            for (int mf = 0; mf < 4; ++mf)
#pragma unroll
                for (int nf = 0; nf < 4; ++nf) {
                    asm volatile(
                        "mma.sync.aligned.m16n8k8.row.col.f32.tf32.tf32.f32 "
                        "{%0,%1,%2,%3}, {%4,%5,%6,%7}, {%8,%9}, {%0,%1,%2,%3};"
                        : "+f"(acc[mf][nf][0]), "+f"(acc[mf][nf][1]),
                          "+f"(acc[mf][nf][2]), "+f"(acc[mf][nf][3])
                        : "r"(af[mf][0]), "r"(af[mf][1]), "r"(af[mf][2]), "r"(af[mf][3]),
                          "r"(bf[nf][0]), "r"(bf[nf][1]));
                }
        }
        __syncthreads();
    }

    // epilogue
#pragma unroll
    for (int mf = 0; mf < 4; ++mf) {
        int r0 = m0 + wm + mf * 16 + gid;
#pragma unroll
        for (int nf = 0; nf < 4; ++nf) {
            int c = n0 + wn + nf * 8 + tig * 2;
#pragma unroll
            for (int half = 0; half < 2; ++half) {
                int r = r0 + half * 8;
                float v0 = acc[mf][nf][half * 2 + 0];
                float v1 = acc[mf][nf][half * 2 + 1];
                if (EPI >= 1) { v0 += bias[c]; v1 += bias[c + 1]; }
                if (EPI == 2) { v0 = gelu_exact(v0); v1 = gelu_exact(v1); }
                size_t off = (size_t)r * N + c;
                if (EPI == 1) { v0 += res[off]; v1 += res[off + 1]; }
                *(float2*)(C + off) = make_float2(v0, v1);
            }
        }
    }
}

// ---------------- column softmax (axis = query i) + p * v^T + head concat ----------------
// s layout (H,B,L,L); v layout (H, B*L, A); att out: (B*L, D) with att[b*L+i][h*A + j]
__global__ void softmax_att_kernel(const float* __restrict__ s,
                                   const float* __restrict__ v,
                                   float* __restrict__ att)
{
    int z = blockIdx.y;          // z = h*B + b
    int h = z >> 3, b = z & 7;
    int j0 = blockIdx.x * 32;
    int tx = threadIdx.x, ty = threadIdx.y;   // 32 x 16
    const float* sp = s + (size_t)z * LL * LL;
    const float rs = 0.04419417382415922f;    // 1/sqrt(512)
    int j = j0 + tx;

    // pass 1: column sums of exp
    float part = 0.f;
    for (int it = 0; it < 32; ++it) {
        int i = it * 16 + ty;
        float val = (j <= i) ? sp[(size_t)i * LL + j] : -1000.f;
        part += expf(val * rs);
    }
    __shared__ float red[16][32];
    __shared__ float cinv[32];
    red[ty][tx] = part; __syncthreads();
    if (ty < 8) red[ty][tx] += red[ty + 8][tx];
    __syncthreads();
    if (ty < 4) red[ty][tx] += red[ty + 4][tx];
    __syncthreads();
    if (ty < 2) red[ty][tx] += red[ty + 2][tx];
    __syncthreads();
    if (ty == 0) cinv[tx] = 1.f / (red[0][tx] + red[1][tx]);
    __syncthreads();
    float ci = cinv[tx];

    // pass 2: p = exp/sum, att[b,i,h*A + j] = p(i,j) * v[h, b*L + j, i]
    __shared__ float vt[32][17];
    const float* vp = v + ((size_t)z * LL + j0) * AA;   // row (h*B*L + b*L + j0)
    size_t attbase = (size_t)b * LL * DD + (size_t)h * AA + j0;
    int tid = ty * 32 + tx;
    int vr = tid >> 4, vc = tid & 15;
    for (int it = 0; it < 32; ++it) {
        __syncthreads();
        vt[vr][vc] = vp[(size_t)vr * AA + it * 16 + vc];
        __syncthreads();
        int i = it * 16 + ty;
        float val = (j <= i) ? sp[(size_t)i * LL + j] : -1000.f;
        float p = expf(val * rs) * ci;
        att[attbase + (size_t)i * DD + tx] = p * vt[tx][ty];
    }
}

// ---------------- launch ----------------
extern "C" void kernel_launch(void* const* d_in, const int* in_sizes, int n_in,
                              void* d_out, int out_size)
{
    (void)in_sizes; (void)n_in; (void)out_size;
    const float* x    = (const float*)d_in[0];
    // d_in[1] = mask (bool tril) -- applied analytically
    const float* Wq   = (const float*)d_in[2];
    const float* Wk   = (const float*)d_in[3];
    const float* Wv   = (const float*)d_in[4];
    const float* fc_w = (const float*)d_in[5];
    const float* fc_b = (const float*)d_in[6];
    const float* ln1g = (const float*)d_in[7];
    const float* ln1b = (const float*)d_in[8];
    const float* W1   = (const float*)d_in[9];
    const float* b1   = (const float*)d_in[10];
    const float* W2   = (const float*)d_in[11];
    const float* b2   = (const float*)d_in[12];
    const float* ln2g = (const float*)d_in[13];
    const float* ln2b = (const float*)d_in[14];
    float* out = (float*)d_out;

    float *xn, *q, *k, *v, *s, *att, *x1, *hb;
    cudaGetSymbolAddress((void**)&xn,  g_xn);
    cudaGetSymbolAddress((void**)&q,   g_q);
    cudaGetSymbolAddress((void**)&k,   g_k);
    cudaGetSymbolAddress((void**)&v,   g_v);
    cudaGetSymbolAddress((void**)&s,   g_s);
    cudaGetSymbolAddress((void**)&att, g_att);
    cudaGetSymbolAddress((void**)&x1,  g_x1);
    cudaGetSymbolAddress((void**)&hb,  g_h);

    const int M = BB * LL;   // 4096

    // 1) ln1
    ln_kernel<<<M, 256>>>(x, ln1g, ln1b, xn);

    // 2) QKV: per-head GEMMs, z = head. A stride 0 (shared xn).
    {
        dim3 grid(AA / 128, M / 128, HH);
        long long sBq = (long long)DD * AA;     // per-head weight block
        long long sCq = (long long)M * AA;      // per-head output block
        gemm_tf32<0, false, 136><<<grid, 256>>>(xn, Wq, q, nullptr, nullptr, M, AA, DD, 0, sBq, sCq);
        gemm_tf32<0, false, 136><<<grid, 256>>>(xn, Wk, k, nullptr, nullptr, M, AA, DD, 0, sBq, sCq);
        gemm_tf32<0, false, 136><<<grid, 256>>>(xn, Wv, v, nullptr, nullptr, M, AA, DD, 0, sBq, sCq);
    }

    // 3) s = q @ k^T, 64 batches (z = h*B + b), all strides L*A = L*L
    {
        dim3 grid(LL / 128, LL / 128, HH * BB);
        long long st = (long long)LL * AA;
        gemm_tf32<0, true, 132><<<grid, 256>>>(q, k, s, nullptr, nullptr, LL, LL, AA, st, st, st);
    }

    // 4) column softmax + p*v^T + head concat -> att (B*L, D)
    {
        dim3 grid(LL / 32, HH * BB);
        dim3 blk(32, 16);
        softmax_att_kernel<<<grid, blk>>>(s, v, att);
    }

    // 5) x1 = x + att @ fc_w + fc_b
    {
        dim3 grid(DD / 128, M / 128, 1);
        gemm_tf32<1, false, 136><<<grid, 256>>>(att, fc_w, x1, fc_b, x, M, DD, DD, 0, 0, 0);
    }

    // 6) ln2 (reuse xn)
    ln_kernel<<<M, 256>>>(x1, ln2g, ln2b, xn);

    // 7) h = gelu(xn @ W1 + b1)
    {
        dim3 grid(FF / 128, M / 128, 1);
        gemm_tf32<2, false, 136><<<grid, 256>>>(xn, W1, hb, b1, nullptr, M, FF, DD, 0, 0, 0);
    }

    // 8) out = x1 + h @ W2 + b2
    {
        dim3 grid(DD / 128, M / 128, 1);
        gemm_tf32<1, false, 136><<<grid, 256>>>(hb, W2, out, b2, x1, M, DD, FF, 0, 0, 0);
    }
}

// round 2
// speedup vs baseline: 1.3211x; 1.3211x over previous
#include <cuda_runtime.h>
#include <cstdint>
#include <math.h>

#define BB 8
#define LL 512
#define DD 4096
#define HH 8
#define FF 16384
#define AA 512   // per-head dim == L

// ---------------- scratch (device globals: allocation-free) ----------------
__device__ float g_xn [BB*LL*DD];
__device__ float g_q  [HH*BB*LL*AA];
__device__ float g_k  [HH*BB*LL*AA];
__device__ float g_v  [HH*BB*LL*AA];
__device__ float g_s  [HH*BB*LL*LL];
__device__ float g_att[BB*LL*DD];
__device__ float g_x1 [BB*LL*DD];
__device__ float g_h  [BB*LL*FF];

// ---------------- helpers ----------------
__device__ __forceinline__ uint32_t f2tf(float f) {
    uint32_t r;
    asm("cvt.rna.tf32.f32 %0, %1;" : "=r"(r) : "f"(f));
    return r;
}
__device__ __forceinline__ float gelu_exact(float x) {
    return 0.5f * x * (1.0f + erff(x * 0.7071067811865475f));
}
__device__ __forceinline__ uint32_t sptr(const void* p) {
    return (uint32_t)__cvta_generic_to_shared(p);
}
__device__ __forceinline__ void cp16(void* dst, const void* src) {
    asm volatile("cp.async.cg.shared.global [%0], [%1], 16;" :: "r"(sptr(dst)), "l"(src));
}
__device__ __forceinline__ void cp_commit() {
    asm volatile("cp.async.commit_group;");
}
__device__ __forceinline__ void cp_wait1() {
    asm volatile("cp.async.wait_group 1;");
}

// ---------------- layernorm ----------------
__global__ void ln_kernel(const float* __restrict__ x,
                          const float* __restrict__ g,
                          const float* __restrict__ b,
                          float* __restrict__ out)
{
    int row = blockIdx.x;
    const float4* xr = (const float4*)(x + (size_t)row * DD);
    __shared__ float red[256];
    float4 vals[4];
    float s = 0.f;
#pragma unroll
    for (int it = 0; it < 4; ++it) {
        float4 v = xr[threadIdx.x + it * 256];
        vals[it] = v;
        s += v.x + v.y + v.z + v.w;
    }
    red[threadIdx.x] = s; __syncthreads();
    for (int st = 128; st > 0; st >>= 1) {
        if (threadIdx.x < st) red[threadIdx.x] += red[threadIdx.x + st];
        __syncthreads();
    }
    float mean = red[0] * (1.f / DD);
    __syncthreads();
    float vs = 0.f;
#pragma unroll
    for (int it = 0; it < 4; ++it) {
        float4 v = vals[it];
        float dx = v.x - mean, dy = v.y - mean, dz = v.z - mean, dw = v.w - mean;
        vs += dx*dx + dy*dy + dz*dz + dw*dw;
    }
    red[threadIdx.x] = vs; __syncthreads();
    for (int st = 128; st > 0; st >>= 1) {
        if (threadIdx.x < st) red[threadIdx.x] += red[threadIdx.x + st];
        __syncthreads();
    }
    float rstd = rsqrtf(red[0] * (1.f / DD) + 1e-5f);
    float4* o = (float4*)(out + (size_t)row * DD);
#pragma unroll
    for (int it = 0; it < 4; ++it) {
        int c = (threadIdx.x + it * 256) * 4;
        float4 v = vals[it];
        float4 gg = *(const float4*)(g + c);
        float4 bb = *(const float4*)(b + c);
        float4 r;
        r.x = (v.x - mean) * rstd * gg.x + bb.x;
        r.y = (v.y - mean) * rstd * gg.y + bb.y;
        r.z = (v.z - mean) * rstd * gg.z + bb.z;
        r.w = (v.w - mean) * rstd * gg.w + bb.w;
        o[threadIdx.x + it * 256] = r;
    }
}

// =====================================================================
// Pipelined NN tf32 GEMM: C = A @ B (+bias)(+gelu)(+residual)
// A (M,K) rm, B (K,N) rm. 128x128x32 tile, 256 thr, cp.async 2-stage.
// smem holds RAW f32; cvt.rna to tf32 at fragment load.
// EPI: 0 none, 1 bias+res, 2 bias+gelu
// =====================================================================
#define LDAS 36
#define LDBS 136
#define A_TILE (128 * LDAS)
#define B_TILE (32 * LDBS)
#define NN_SMEM ((2 * (A_TILE + B_TILE)) * 4)

template<int EPI>
__global__ void __launch_bounds__(256, 2)
gemm_nn_pipe(const float* __restrict__ A, const float* __restrict__ B,
             float* __restrict__ C, const float* __restrict__ bias,
             const float* __restrict__ res,
             int M, int N, int K,
             long long sA, long long sB, long long sC)
{
    extern __shared__ float smem[];
    float* As = smem;                 // 2 * A_TILE
    float* Bs = smem + 2 * A_TILE;    // 2 * B_TILE

    int z = blockIdx.z;
    A += (long long)z * sA;
    B += (long long)z * sB;
    C += (long long)z * sC;

    int m0 = blockIdx.y * 128, n0 = blockIdx.x * 128;
    int tid = threadIdx.x;
    int warp = tid >> 5, lane = tid & 31;
    int wm = (warp >> 2) * 64, wn = (warp & 3) * 32;
    int gid = lane >> 2, tig = lane & 3;

    // loader indices (precompute)
    int a_rm = tid >> 3, a_c4 = (tid & 7) * 4;          // + it*32 rows
    int b_rk = tid >> 5, b_c4 = (tid & 31) * 4;         // + it*8 rows

    float acc[4][4][4];
#pragma unroll
    for (int a = 0; a < 4; ++a)
#pragma unroll
        for (int b = 0; b < 4; ++b)
#pragma unroll
            for (int c = 0; c < 4; ++c) acc[a][b][c] = 0.f;

    const int kTiles = K >> 5;

    // ---- issue load for tile 0 into stage 0 ----
    {
        const float* Ag = A + (size_t)(m0 + a_rm) * K + a_c4;
        const float* Bg = B + (size_t)b_rk * N + n0 + b_c4;
        float* Ad = As + a_rm * LDAS + a_c4;
        float* Bd = Bs + b_rk * LDBS + b_c4;
#pragma unroll
        for (int it = 0; it < 4; ++it) {
            cp16(Ad + it * 32 * LDAS, Ag + (size_t)it * 32 * K);
            cp16(Bd + it * 8 * LDBS, Bg + (size_t)it * 8 * N);
        }
    }
    cp_commit();

    for (int t = 0; t < kTiles; ++t) {
        // issue load for tile t+1 into stage (t+1)&1
        if (t + 1 < kTiles) {
            int kt = (t + 1) << 5;
            int st = (t + 1) & 1;
            const float* Ag = A + (size_t)(m0 + a_rm) * K + kt + a_c4;
            const float* Bg = B + (size_t)(kt + b_rk) * N + n0 + b_c4;
            float* Ad = As + st * A_TILE + a_rm * LDAS + a_c4;
            float* Bd = Bs + st * B_TILE + b_rk * LDBS + b_c4;
#pragma unroll
            for (int it = 0; it < 4; ++it) {
                cp16(Ad + it * 32 * LDAS, Ag + (size_t)it * 32 * K);
                cp16(Bd + it * 8 * LDBS, Bg + (size_t)it * 8 * N);
            }
        }
        cp_commit();
        cp_wait1();          // tile t resident
        __syncthreads();

        const float* As_s = As + (t & 1) * A_TILE;
        const float* Bs_s = Bs + (t & 1) * B_TILE;

#pragma unroll
        for (int ks = 0; ks < 4; ++ks) {
            uint32_t af[4][4], bf[4][2];
#pragma unroll
            for (int mf = 0; mf < 4; ++mf) {
                const float* p = &As_s[(wm + mf * 16 + gid) * LDAS + ks * 8 + tig];
                af[mf][0] = f2tf(p[0]);
                af[mf][1] = f2tf(p[8 * LDAS]);
                af[mf][2] = f2tf(p[4]);
                af[mf][3] = f2tf(p[8 * LDAS + 4]);
            }
#pragma unroll
            for (int nf = 0; nf < 4; ++nf) {
                const float* p = &Bs_s[(ks * 8 + tig) * LDBS + wn + nf * 8 + gid];
                bf[nf][0] = f2tf(p[0]);
                bf[nf][1] = f2tf(p[4 * LDBS]);
            }
#pragma unroll
            for (int mf = 0; mf < 4; ++mf)
#pragma unroll
                for (int nf = 0; nf < 4; ++nf) {
                    asm volatile(
                        "mma.sync.aligned.m16n8k8.row.col.f32.tf32.tf32.f32 "
                        "{%0,%1,%2,%3}, {%4,%5,%6,%7}, {%8,%9}, {%0,%1,%2,%3};"
                        : "+f"(acc[mf][nf][0]), "+f"(acc[mf][nf][1]),
                          "+f"(acc[mf][nf][2]), "+f"(acc[mf][nf][3])
                        : "r"(af[mf][0]), "r"(af[mf][1]), "r"(af[mf][2]), "r"(af[mf][3]),
                          "r"(bf[nf][0]), "r"(bf[nf][1]));
                }
        }
        __syncthreads();   // protect stage (t&1) before next-next issue
    }

    // epilogue
#pragma unroll
    for (int mf = 0; mf < 4; ++mf) {
        int r0 = m0 + wm + mf * 16 + gid;
#pragma unroll
        for (int nf = 0; nf < 4; ++nf) {
            int c = n0 + wn + nf * 8 + tig * 2;
#pragma unroll
            for (int half = 0; half < 2; ++half) {
                int r = r0 + half * 8;
                float v0 = acc[mf][nf][half * 2 + 0];
                float v1 = acc[mf][nf][half * 2 + 1];
                if (EPI >= 1) { v0 += bias[c]; v1 += bias[c + 1]; }
                if (EPI == 2) { v0 = gelu_exact(v0); v1 = gelu_exact(v1); }
                size_t off = (size_t)r * N + c;
                if (EPI == 1) { v0 += res[off]; v1 += res[off + 1]; }
                *(float2*)(C + off) = make_float2(v0, v1);
            }
        }
    }
}

// =====================================================================
// Synchronous BT GEMM (A @ B^T) — only for S = Q K^T (1% of FLOPs)
// =====================================================================
template<int LDBT>
__global__ void __launch_bounds__(256, 2)
gemm_bt(const float* __restrict__ A, const float* __restrict__ B,
        float* __restrict__ C,
        int M, int N, int K,
        long long sA, long long sB, long long sC)
{
    __shared__ uint32_t As[128 * LDAS];
    __shared__ uint32_t Bs[32 * LDBT];

    int z = blockIdx.z;
    A += (long long)z * sA;
    B += (long long)z * sB;
    C += (long long)z * sC;

    int m0 = blockIdx.y * 128, n0 = blockIdx.x * 128;
    int tid = threadIdx.x;
    int warp = tid >> 5, lane = tid & 31;
    int wm = (warp >> 2) * 64, wn = (warp & 3) * 32;
    int gid = lane >> 2, tig = lane & 3;

    float acc[4][4][4];
#pragma unroll
    for (int a = 0; a < 4; ++a)
#pragma unroll
        for (int b = 0; b < 4; ++b)
#pragma unroll
            for (int c = 0; c < 4; ++c) acc[a][b][c] = 0.f;

    for (int kt = 0; kt < K; kt += 32) {
#pragma unroll
        for (int it = 0; it < 4; ++it) {
            int idx = tid + it * 256;
            int rm = idx >> 3, c4 = idx & 7;
            float4 v = *(const float4*)(A + (size_t)(m0 + rm) * K + kt + c4 * 4);
            uint32_t* dst = &As[rm * LDAS + c4 * 4];
            dst[0] = f2tf(v.x); dst[1] = f2tf(v.y); dst[2] = f2tf(v.z); dst[3] = f2tf(v.w);
        }
#pragma unroll
        for (int it = 0; it < 4; ++it) {
            int idx = tid + it * 256;
            int rn = idx >> 3, c4 = idx & 7;
            float4 v = *(const float4*)(B + (size_t)(n0 + rn) * K + kt + c4 * 4);
            Bs[(c4 * 4 + 0) * LDBT + rn] = f2tf(v.x);
            Bs[(c4 * 4 + 1) * LDBT + rn] = f2tf(v.y);
            Bs[(c4 * 4 + 2) * LDBT + rn] = f2tf(v.z);
            Bs[(c4 * 4 + 3) * LDBT + rn] = f2tf(v.w);
        }
        __syncthreads();

#pragma unroll
        for (int ks = 0; ks < 4; ++ks) {
            uint32_t af[4][4], bf[4][2];
#pragma unroll
            for (int mf = 0; mf < 4; ++mf) {
                const uint32_t* p = &As[(wm + mf * 16 + gid) * LDAS + ks * 8 + tig];
                af[mf][0] = p[0];
                af[mf][1] = p[8 * LDAS];
                af[mf][2] = p[4];
                af[mf][3] = p[8 * LDAS + 4];
            }
#pragma unroll
            for (int nf = 0; nf < 4; ++nf) {
                const uint32_t* p = &Bs[(ks * 8 + tig) * LDBT + wn + nf * 8 + gid];
                bf[nf][0] = p[0];
                bf[nf][1] = p[4 * LDBT];
            }
#pragma unroll
            for (int mf = 0; mf < 4; ++mf)
#pragma unroll
                for (int nf = 0; nf < 4; ++nf) {
                    asm volatile(
                        "mma.sync.aligned.m16n8k8.row.col.f32.tf32.tf32.f32 "
                        "{%0,%1,%2,%3}, {%4,%5,%6,%7}, {%8,%9}, {%0,%1,%2,%3};"
                        : "+f"(acc[mf][nf][0]), "+f"(acc[mf][nf][1]),
                          "+f"(acc[mf][nf][2]), "+f"(acc[mf][nf][3])
                        : "r"(af[mf][0]), "r"(af[mf][1]), "r"(af[mf][2]), "r"(af[mf][3]),
                          "r"(bf[nf][0]), "r"(bf[nf][1]));
                }
        }
        __syncthreads();
    }

#pragma unroll
    for (int mf = 0; mf < 4; ++mf) {
        int r0 = m0 + wm + mf * 16 + gid;
#pragma unroll
        for (int nf = 0; nf < 4; ++nf) {
            int c = n0 + wn + nf * 8 + tig * 2;
#pragma unroll
            for (int half = 0; half < 2; ++half) {
                int r = r0 + half * 8;
                size_t off = (size_t)r * N + c;
                *(float2*)(C + off) = make_float2(acc[mf][nf][half * 2 + 0],
                                                  acc[mf][nf][half * 2 + 1]);
            }
        }
    }
}

// ---------------- column softmax + p * v^T + head concat ----------------
__global__ void softmax_att_kernel(const float* __restrict__ s,
                                   const float* __restrict__ v,
                                   float* __restrict__ att)
{
    int z = blockIdx.y;          // z = h*B + b
    int h = z >> 3, b = z & 7;
    int j0 = blockIdx.x * 32;
    int tx = threadIdx.x, ty = threadIdx.y;   // 32 x 16
    const float* sp = s + (size_t)z * LL * LL;
    const float rs = 0.04419417382415922f;    // 1/sqrt(512)
    int j = j0 + tx;

    float part = 0.f;
    for (int it = 0; it < 32; ++it) {
        int i = it * 16 + ty;
        float val = (j <= i) ? sp[(size_t)i * LL + j] : -1000.f;
        part += expf(val * rs);
    }
    __shared__ float red[16][32];
    __shared__ float cinv[32];
    red[ty][tx] = part; __syncthreads();
    if (ty < 8) red[ty][tx] += red[ty + 8][tx];
    __syncthreads();
    if (ty < 4) red[ty][tx] += red[ty + 4][tx];
    __syncthreads();
    if (ty < 2) red[ty][tx] += red[ty + 2][tx];
    __syncthreads();
    if (ty == 0) cinv[tx] = 1.f / (red[0][tx] + red[1][tx]);
    __syncthreads();
    float ci = cinv[tx];

    __shared__ float vt[32][17];
    const float* vp = v + ((size_t)z * LL + j0) * AA;
    size_t attbase = (size_t)b * LL * DD + (size_t)h * AA + j0;
    int tid = ty * 32 + tx;
    int vr = tid >> 4, vc = tid & 15;
    for (int it = 0; it < 32; ++it) {
        __syncthreads();
        vt[vr][vc] = vp[(size_t)vr * AA + it * 16 + vc];
        __syncthreads();
        int i = it * 16 + ty;
        float val = (j <= i) ? sp[(size_t)i * LL + j] : -1000.f;
        float p = expf(val * rs) * ci;
        att[attbase + (size_t)i * DD + tx] = p * vt[tx][ty];
    }
}

// ---------------- launch ----------------
extern "C" void kernel_launch(void* const* d_in, const int* in_sizes, int n_in,
                              void* d_out, int out_size)
{
    (void)in_sizes; (void)n_in; (void)out_size;
    const float* x    = (const float*)d_in[0];
    const float* Wq   = (const float*)d_in[2];
    const float* Wk   = (const float*)d_in[3];
    const float* Wv   = (const float*)d_in[4];
    const float* fc_w = (const float*)d_in[5];
    const float* fc_b = (const float*)d_in[6];
    const float* ln1g = (const float*)d_in[7];
    const float* ln1b = (const float*)d_in[8];
    const float* W1   = (const float*)d_in[9];
    const float* b1   = (const float*)d_in[10];
    const float* W2   = (const float*)d_in[11];
    const float* b2   = (const float*)d_in[12];
    const float* ln2g = (const float*)d_in[13];
    const float* ln2b = (const float*)d_in[14];
    float* out = (float*)d_out;

    float *xn, *q, *k, *v, *s, *att, *x1, *hb;
    cudaGetSymbolAddress((void**)&xn,  g_xn);
    cudaGetSymbolAddress((void**)&q,   g_q);
    cudaGetSymbolAddress((void**)&k,   g_k);
    cudaGetSymbolAddress((void**)&v,   g_v);
    cudaGetSymbolAddress((void**)&s,   g_s);
    cudaGetSymbolAddress((void**)&att, g_att);
    cudaGetSymbolAddress((void**)&x1,  g_x1);
    cudaGetSymbolAddress((void**)&hb,  g_h);

    cudaFuncSetAttribute(gemm_nn_pipe<0>, cudaFuncAttributeMaxDynamicSharedMemorySize, NN_SMEM);
    cudaFuncSetAttribute(gemm_nn_pipe<1>, cudaFuncAttributeMaxDynamicSharedMemorySize, NN_SMEM);
    cudaFuncSetAttribute(gemm_nn_pipe<2>, cudaFuncAttributeMaxDynamicSharedMemorySize, NN_SMEM);

    const int M = BB * LL;   // 4096

    // 1) ln1
    ln_kernel<<<M, 256>>>(x, ln1g, ln1b, xn);

    // 2) QKV per-head GEMMs (z = head)
    {
        dim3 grid(AA / 128, M / 128, HH);
        long long sBq = (long long)DD * AA;
        long long sCq = (long long)M * AA;
        gemm_nn_pipe<0><<<grid, 256, NN_SMEM>>>(xn, Wq, q, nullptr, nullptr, M, AA, DD, 0, sBq, sCq);
        gemm_nn_pipe<0><<<grid, 256, NN_SMEM>>>(xn, Wk, k, nullptr, nullptr, M, AA, DD, 0, sBq, sCq);
        gemm_nn_pipe<0><<<grid, 256, NN_SMEM>>>(xn, Wv, v, nullptr, nullptr, M, AA, DD, 0, sBq, sCq);
    }

    // 3) s = q @ k^T (64 batches)
    {
        dim3 grid(LL / 128, LL / 128, HH * BB);
        long long st = (long long)LL * AA;
        gemm_bt<132><<<grid, 256>>>(q, k, s, LL, LL, AA, st, st, st);
    }

    // 4) column softmax + p*v^T + concat
    {
        dim3 grid(LL / 32, HH * BB);
        dim3 blk(32, 16);
        softmax_att_kernel<<<grid, blk>>>(s, v, att);
    }

    // 5) x1 = x + att @ fc_w + fc_b
    {
        dim3 grid(DD / 128, M / 128, 1);
        gemm_nn_pipe<1><<<grid, 256, NN_SMEM>>>(att, fc_w, x1, fc_b, x, M, DD, DD, 0, 0, 0);
    }

    // 6) ln2
    ln_kernel<<<M, 256>>>(x1, ln2g, ln2b, xn);

    // 7) h = gelu(xn @ W1 + b1)
    {
        dim3 grid(FF / 128, M / 128, 1);
        gemm_nn_pipe<2><<<grid, 256, NN_SMEM>>>(xn, W1, hb, b1, nullptr, M, FF, DD, 0, 0, 0);
    }

    // 8) out = x1 + h @ W2 + b2
    {
        dim3 grid(DD / 128, M / 128, 1);
        gemm_nn_pipe<1><<<grid, 256, NN_SMEM>>>(hb, W2, out, b2, x1, M, DD, FF, 0, 0, 0);
    }
}

// round 3
// speedup vs baseline: 1.3937x; 1.0549x over previous
#include <cuda_runtime.h>
#include <cstdint>
#include <math.h>

#define BB 8
#define LL 512
#define DD 4096
#define HH 8
#define FF 16384
#define AA 512   // per-head dim == L

// ---------------- scratch (device globals: allocation-free) ----------------
__device__ float g_xn [BB*LL*DD];
__device__ float g_q  [HH*BB*LL*AA];
__device__ float g_k  [HH*BB*LL*AA];
__device__ float g_v  [HH*BB*LL*AA];
__device__ float g_s  [HH*BB*LL*LL];
__device__ float g_att[BB*LL*DD];
__device__ float g_x1 [BB*LL*DD];
__device__ float g_h  [BB*LL*FF];
// tf32-rounded weight copies
__device__ float g_wq [HH*DD*AA];
__device__ float g_wk [HH*DD*AA];
__device__ float g_wv [HH*DD*AA];
__device__ float g_wfc[DD*DD];
__device__ float g_w1 [DD*FF];
__device__ float g_w2 [FF*DD];

// ---------------- helpers ----------------
__device__ __forceinline__ uint32_t f2tf(float f) {
    uint32_t r;
    asm("cvt.rna.tf32.f32 %0, %1;" : "=r"(r) : "f"(f));
    return r;
}
__device__ __forceinline__ float roundtf(float f) {
    return __uint_as_float(f2tf(f));
}
__device__ __forceinline__ float gelu_exact(float x) {
    return 0.5f * x * (1.0f + erff(x * 0.7071067811865475f));
}
__device__ __forceinline__ uint32_t sptr(const void* p) {
    return (uint32_t)__cvta_generic_to_shared(p);
}
__device__ __forceinline__ void cp16(void* dst, const void* src) {
    asm volatile("cp.async.cg.shared.global [%0], [%1], 16;" :: "r"(sptr(dst)), "l"(src));
}
__device__ __forceinline__ void cp_commit() {
    asm volatile("cp.async.commit_group;");
}
__device__ __forceinline__ void cp_wait1() {
    asm volatile("cp.async.wait_group 1;");
}

// ---------------- tf32 rounding pass (weights) ----------------
__global__ void round_tf32_kernel(const float4* __restrict__ in,
                                  float4* __restrict__ out, int n4)
{
    int i = blockIdx.x * blockDim.x + threadIdx.x;
    if (i < n4) {
        float4 v = in[i];
        v.x = roundtf(v.x); v.y = roundtf(v.y);
        v.z = roundtf(v.z); v.w = roundtf(v.w);
        out[i] = v;
    }
}

// ---------------- layernorm (output rounded to tf32) ----------------
__global__ void ln_kernel(const float* __restrict__ x,
                          const float* __restrict__ g,
                          const float* __restrict__ b,
                          float* __restrict__ out)
{
    int row = blockIdx.x;
    const float4* xr = (const float4*)(x + (size_t)row * DD);
    __shared__ float red[256];
    float4 vals[4];
    float s = 0.f;
#pragma unroll
    for (int it = 0; it < 4; ++it) {
        float4 v = xr[threadIdx.x + it * 256];
        vals[it] = v;
        s += v.x + v.y + v.z + v.w;
    }
    red[threadIdx.x] = s; __syncthreads();
    for (int st = 128; st > 0; st >>= 1) {
        if (threadIdx.x < st) red[threadIdx.x] += red[threadIdx.x + st];
        __syncthreads();
    }
    float mean = red[0] * (1.f / DD);
    __syncthreads();
    float vs = 0.f;
#pragma unroll
    for (int it = 0; it < 4; ++it) {
        float4 v = vals[it];
        float dx = v.x - mean, dy = v.y - mean, dz = v.z - mean, dw = v.w - mean;
        vs += dx*dx + dy*dy + dz*dz + dw*dw;
    }
    red[threadIdx.x] = vs; __syncthreads();
    for (int st = 128; st > 0; st >>= 1) {
        if (threadIdx.x < st) red[threadIdx.x] += red[threadIdx.x + st];
        __syncthreads();
    }
    float rstd = rsqrtf(red[0] * (1.f / DD) + 1e-5f);
    float4* o = (float4*)(out + (size_t)row * DD);
#pragma unroll
    for (int it = 0; it < 4; ++it) {
        int c = (threadIdx.x + it * 256) * 4;
        float4 v = vals[it];
        float4 gg = *(const float4*)(g + c);
        float4 bb = *(const float4*)(b + c);
        float4 r;
        r.x = roundtf((v.x - mean) * rstd * gg.x + bb.x);
        r.y = roundtf((v.y - mean) * rstd * gg.y + bb.y);
        r.z = roundtf((v.z - mean) * rstd * gg.z + bb.z);
        r.w = roundtf((v.w - mean) * rstd * gg.w + bb.w);
        o[threadIdx.x + it * 256] = r;
    }
}

// =====================================================================
// Pipelined NN tf32 GEMM. Operands are PRE-ROUNDED tf32 in gmem; the
// mainloop has zero CVT instructions (raw bits fed to mma).
// EPI: 0 none, 1 bias+res, 2 bias+gelu (output rounded to tf32)
// =====================================================================
#define LDAS 36
#define LDBS 136
#define A_TILE (128 * LDAS)
#define B_TILE (32 * LDBS)
#define NN_SMEM ((2 * (A_TILE + B_TILE)) * 4)

template<int EPI>
__global__ void __launch_bounds__(256, 2)
gemm_nn_pipe(const float* __restrict__ A, const float* __restrict__ B,
             float* __restrict__ C, const float* __restrict__ bias,
             const float* __restrict__ res,
             int M, int N, int K,
             long long sA, long long sB, long long sC)
{
    extern __shared__ float smem[];
    float* As = smem;
    float* Bs = smem + 2 * A_TILE;

    int z = blockIdx.z;
    A += (long long)z * sA;
    B += (long long)z * sB;
    C += (long long)z * sC;

    int m0 = blockIdx.y * 128, n0 = blockIdx.x * 128;
    int tid = threadIdx.x;
    int warp = tid >> 5, lane = tid & 31;
    int wm = (warp >> 2) * 64, wn = (warp & 3) * 32;
    int gid = lane >> 2, tig = lane & 3;

    int a_rm = tid >> 3, a_c4 = (tid & 7) * 4;
    int b_rk = tid >> 5, b_c4 = (tid & 31) * 4;

    float acc[4][4][4];
#pragma unroll
    for (int a = 0; a < 4; ++a)
#pragma unroll
        for (int b = 0; b < 4; ++b)
#pragma unroll
            for (int c = 0; c < 4; ++c) acc[a][b][c] = 0.f;

    const int kTiles = K >> 5;

    {
        const float* Ag = A + (size_t)(m0 + a_rm) * K + a_c4;
        const float* Bg = B + (size_t)b_rk * N + n0 + b_c4;
        float* Ad = As + a_rm * LDAS + a_c4;
        float* Bd = Bs + b_rk * LDBS + b_c4;
#pragma unroll
        for (int it = 0; it < 4; ++it) {
            cp16(Ad + it * 32 * LDAS, Ag + (size_t)it * 32 * K);
            cp16(Bd + it * 8 * LDBS, Bg + (size_t)it * 8 * N);
        }
    }
    cp_commit();

    for (int t = 0; t < kTiles; ++t) {
        if (t + 1 < kTiles) {
            int kt = (t + 1) << 5;
            int st = (t + 1) & 1;
            const float* Ag = A + (size_t)(m0 + a_rm) * K + kt + a_c4;
            const float* Bg = B + (size_t)(kt + b_rk) * N + n0 + b_c4;
            float* Ad = As + st * A_TILE + a_rm * LDAS + a_c4;
            float* Bd = Bs + st * B_TILE + b_rk * LDBS + b_c4;
#pragma unroll
            for (int it = 0; it < 4; ++it) {
                cp16(Ad + it * 32 * LDAS, Ag + (size_t)it * 32 * K);
                cp16(Bd + it * 8 * LDBS, Bg + (size_t)it * 8 * N);
            }
        }
        cp_commit();
        cp_wait1();
        __syncthreads();

        const float* As_s = As + (t & 1) * A_TILE;
        const float* Bs_s = Bs + (t & 1) * B_TILE;

#pragma unroll
        for (int ks = 0; ks < 4; ++ks) {
            uint32_t af[4][4], bf[4][2];
#pragma unroll
            for (int mf = 0; mf < 4; ++mf) {
                const float* p = &As_s[(wm + mf * 16 + gid) * LDAS + ks * 8 + tig];
                af[mf][0] = __float_as_uint(p[0]);
                af[mf][1] = __float_as_uint(p[8 * LDAS]);
                af[mf][2] = __float_as_uint(p[4]);
                af[mf][3] = __float_as_uint(p[8 * LDAS + 4]);
            }
#pragma unroll
            for (int nf = 0; nf < 4; ++nf) {
                const float* p = &Bs_s[(ks * 8 + tig) * LDBS + wn + nf * 8 + gid];
                bf[nf][0] = __float_as_uint(p[0]);
                bf[nf][1] = __float_as_uint(p[4 * LDBS]);
            }
#pragma unroll
            for (int mf = 0; mf < 4; ++mf)
#pragma unroll
                for (int nf = 0; nf < 4; ++nf) {
                    asm volatile(
                        "mma.sync.aligned.m16n8k8.row.col.f32.tf32.tf32.f32 "
                        "{%0,%1,%2,%3}, {%4,%5,%6,%7}, {%8,%9}, {%0,%1,%2,%3};"
                        : "+f"(acc[mf][nf][0]), "+f"(acc[mf][nf][1]),
                          "+f"(acc[mf][nf][2]), "+f"(acc[mf][nf][3])
                        : "r"(af[mf][0]), "r"(af[mf][1]), "r"(af[mf][2]), "r"(af[mf][3]),
                          "r"(bf[nf][0]), "r"(bf[nf][1]));
                }
        }
        __syncthreads();
    }

#pragma unroll
    for (int mf = 0; mf < 4; ++mf) {
        int r0 = m0 + wm + mf * 16 + gid;
#pragma unroll
        for (int nf = 0; nf < 4; ++nf) {
            int c = n0 + wn + nf * 8 + tig * 2;
#pragma unroll
            for (int half = 0; half < 2; ++half) {
                int r = r0 + half * 8;
                float v0 = acc[mf][nf][half * 2 + 0];
                float v1 = acc[mf][nf][half * 2 + 1];
                if (EPI >= 1) { v0 += bias[c]; v1 += bias[c + 1]; }
                if (EPI == 2) {
                    v0 = roundtf(gelu_exact(v0));
                    v1 = roundtf(gelu_exact(v1));
                }
                size_t off = (size_t)r * N + c;
                if (EPI == 1) { v0 += res[off]; v1 += res[off + 1]; }
                *(float2*)(C + off) = make_float2(v0, v1);
            }
        }
    }
}

// =====================================================================
// Synchronous BT GEMM (A @ B^T) — only for S = Q K^T (1% of FLOPs)
// =====================================================================
template<int LDBT>
__global__ void __launch_bounds__(256, 2)
gemm_bt(const float* __restrict__ A, const float* __restrict__ B,
        float* __restrict__ C,
        int M, int N, int K,
        long long sA, long long sB, long long sC)
{
    __shared__ uint32_t As[128 * LDAS];
    __shared__ uint32_t Bs[32 * LDBT];

    int z = blockIdx.z;
    A += (long long)z * sA;
    B += (long long)z * sB;
    C += (long long)z * sC;

    int m0 = blockIdx.y * 128, n0 = blockIdx.x * 128;
    int tid = threadIdx.x;
    int warp = tid >> 5, lane = tid & 31;
    int wm = (warp >> 2) * 64, wn = (warp & 3) * 32;
    int gid = lane >> 2, tig = lane & 3;

    float acc[4][4][4];
#pragma unroll
    for (int a = 0; a < 4; ++a)
#pragma unroll
        for (int b = 0; b < 4; ++b)
#pragma unroll
            for (int c = 0; c < 4; ++c) acc[a][b][c] = 0.f;

    for (int kt = 0; kt < K; kt += 32) {
#pragma unroll
        for (int it = 0; it < 4; ++it) {
            int idx = tid + it * 256;
            int rm = idx >> 3, c4 = idx & 7;
            float4 v = *(const float4*)(A + (size_t)(m0 + rm) * K + kt + c4 * 4);
            uint32_t* dst = &As[rm * LDAS + c4 * 4];
            dst[0] = f2tf(v.x); dst[1] = f2tf(v.y); dst[2] = f2tf(v.z); dst[3] = f2tf(v.w);
        }
#pragma unroll
        for (int it = 0; it < 4; ++it) {
            int idx = tid + it * 256;
            int rn = idx >> 3, c4 = idx & 7;
            float4 v = *(const float4*)(B + (size_t)(n0 + rn) * K + kt + c4 * 4);
            Bs[(c4 * 4 + 0) * LDBT + rn] = f2tf(v.x);
            Bs[(c4 * 4 + 1) * LDBT + rn] = f2tf(v.y);
            Bs[(c4 * 4 + 2) * LDBT + rn] = f2tf(v.z);
            Bs[(c4 * 4 + 3) * LDBT + rn] = f2tf(v.w);
        }
        __syncthreads();

#pragma unroll
        for (int ks = 0; ks < 4; ++ks) {
            uint32_t af[4][4], bf[4][2];
#pragma unroll
            for (int mf = 0; mf < 4; ++mf) {
                const uint32_t* p = &As[(wm + mf * 16 + gid) * LDAS + ks * 8 + tig];
                af[mf][0] = p[0];
                af[mf][1] = p[8 * LDAS];
                af[mf][2] = p[4];
                af[mf][3] = p[8 * LDAS + 4];
            }
#pragma unroll
            for (int nf = 0; nf < 4; ++nf) {
                const uint32_t* p = &Bs[(ks * 8 + tig) * LDBT + wn + nf * 8 + gid];
                bf[nf][0] = p[0];
                bf[nf][1] = p[4 * LDBT];
            }
#pragma unroll
            for (int mf = 0; mf < 4; ++mf)
#pragma unroll
                for (int nf = 0; nf < 4; ++nf) {
                    asm volatile(
                        "mma.sync.aligned.m16n8k8.row.col.f32.tf32.tf32.f32 "
                        "{%0,%1,%2,%3}, {%4,%5,%6,%7}, {%8,%9}, {%0,%1,%2,%3};"
                        : "+f"(acc[mf][nf][0]), "+f"(acc[mf][nf][1]),
                          "+f"(acc[mf][nf][2]), "+f"(acc[mf][nf][3])
                        : "r"(af[mf][0]), "r"(af[mf][1]), "r"(af[mf][2]), "r"(af[mf][3]),
                          "r"(bf[nf][0]), "r"(bf[nf][1]));
                }
        }
        __syncthreads();
    }

#pragma unroll
    for (int mf = 0; mf < 4; ++mf) {
        int r0 = m0 + wm + mf * 16 + gid;
#pragma unroll
        for (int nf = 0; nf < 4; ++nf) {
            int c = n0 + wn + nf * 8 + tig * 2;
#pragma unroll
            for (int half = 0; half < 2; ++half) {
                int r = r0 + half * 8;
                size_t off = (size_t)r * N + c;
                *(float2*)(C + off) = make_float2(acc[mf][nf][half * 2 + 0],
                                                  acc[mf][nf][half * 2 + 1]);
            }
        }
    }
}

// ---------------- column softmax + p * v^T + head concat (att rounded) ----------------
__global__ void softmax_att_kernel(const float* __restrict__ s,
                                   const float* __restrict__ v,
                                   float* __restrict__ att)
{
    int z = blockIdx.y;          // z = h*B + b
    int h = z >> 3, b = z & 7;
    int j0 = blockIdx.x * 32;
    int tx = threadIdx.x, ty = threadIdx.y;   // 32 x 16
    const float* sp = s + (size_t)z * LL * LL;
    const float rs = 0.04419417382415922f;    // 1/sqrt(512)
    int j = j0 + tx;

    float part = 0.f;
    for (int it = 0; it < 32; ++it) {
        int i = it * 16 + ty;
        float val = (j <= i) ? sp[(size_t)i * LL + j] : -1000.f;
        part += expf(val * rs);
    }
    __shared__ float red[16][32];
    __shared__ float cinv[32];
    red[ty][tx] = part; __syncthreads();
    if (ty < 8) red[ty][tx] += red[ty + 8][tx];
    __syncthreads();
    if (ty < 4) red[ty][tx] += red[ty + 4][tx];
    __syncthreads();
    if (ty < 2) red[ty][tx] += red[ty + 2][tx];
    __syncthreads();
    if (ty == 0) cinv[tx] = 1.f / (red[0][tx] + red[1][tx]);
    __syncthreads();
    float ci = cinv[tx];

    __shared__ float vt[32][17];
    const float* vp = v + ((size_t)z * LL + j0) * AA;
    size_t attbase = (size_t)b * LL * DD + (size_t)h * AA + j0;
    int tid = ty * 32 + tx;
    int vr = tid >> 4, vc = tid & 15;
    for (int it = 0; it < 32; ++it) {
        __syncthreads();
        vt[vr][vc] = vp[(size_t)vr * AA + it * 16 + vc];
        __syncthreads();
        int i = it * 16 + ty;
        float val = (j <= i) ? sp[(size_t)i * LL + j] : -1000.f;
        float p = expf(val * rs) * ci;
        att[attbase + (size_t)i * DD + tx] = roundtf(p * vt[tx][ty]);
    }
}

// ---------------- launch ----------------
extern "C" void kernel_launch(void* const* d_in, const int* in_sizes, int n_in,
                              void* d_out, int out_size)
{
    (void)in_sizes; (void)n_in; (void)out_size;
    const float* x    = (const float*)d_in[0];
    const float* Wq   = (const float*)d_in[2];
    const float* Wk   = (const float*)d_in[3];
    const float* Wv   = (const float*)d_in[4];
    const float* fc_w = (const float*)d_in[5];
    const float* fc_b = (const float*)d_in[6];
    const float* ln1g = (const float*)d_in[7];
    const float* ln1b = (const float*)d_in[8];
    const float* W1   = (const float*)d_in[9];
    const float* b1   = (const float*)d_in[10];
    const float* W2   = (const float*)d_in[11];
    const float* b2   = (const float*)d_in[12];
    const float* ln2g = (const float*)d_in[13];
    const float* ln2b = (const float*)d_in[14];
    float* out = (float*)d_out;

    float *xn, *q, *k, *v, *s, *att, *x1, *hb;
    float *wq, *wk, *wv, *wfc, *w1, *w2;
    cudaGetSymbolAddress((void**)&xn,  g_xn);
    cudaGetSymbolAddress((void**)&q,   g_q);
    cudaGetSymbolAddress((void**)&k,   g_k);
    cudaGetSymbolAddress((void**)&v,   g_v);
    cudaGetSymbolAddress((void**)&s,   g_s);
    cudaGetSymbolAddress((void**)&att, g_att);
    cudaGetSymbolAddress((void**)&x1,  g_x1);
    cudaGetSymbolAddress((void**)&hb,  g_h);
    cudaGetSymbolAddress((void**)&wq,  g_wq);
    cudaGetSymbolAddress((void**)&wk,  g_wk);
    cudaGetSymbolAddress((void**)&wv,  g_wv);
    cudaGetSymbolAddress((void**)&wfc, g_wfc);
    cudaGetSymbolAddress((void**)&w1,  g_w1);
    cudaGetSymbolAddress((void**)&w2,  g_w2);

    cudaFuncSetAttribute(gemm_nn_pipe<0>, cudaFuncAttributeMaxDynamicSharedMemorySize, NN_SMEM);
    cudaFuncSetAttribute(gemm_nn_pipe<1>, cudaFuncAttributeMaxDynamicSharedMemorySize, NN_SMEM);
    cudaFuncSetAttribute(gemm_nn_pipe<2>, cudaFuncAttributeMaxDynamicSharedMemorySize, NN_SMEM);

    const int M = BB * LL;   // 4096

    // 0) tf32-round weights into scratch copies
    {
        int t = 256;
        int nqkv = HH * DD * AA / 4;
        round_tf32_kernel<<<nqkv / t, t>>>((const float4*)Wq, (float4*)wq, nqkv);
        round_tf32_kernel<<<nqkv / t, t>>>((const float4*)Wk, (float4*)wk, nqkv);
        round_tf32_kernel<<<nqkv / t, t>>>((const float4*)Wv, (float4*)wv, nqkv);
        int nfc = DD * DD / 4;
        round_tf32_kernel<<<nfc / t, t>>>((const float4*)fc_w, (float4*)wfc, nfc);
        int nw1 = DD * FF / 4;
        round_tf32_kernel<<<nw1 / t, t>>>((const float4*)W1, (float4*)w1, nw1);
        round_tf32_kernel<<<nw1 / t, t>>>((const float4*)W2, (float4*)w2, nw1);
    }

    // 1) ln1 (output tf32-rounded)
    ln_kernel<<<M, 256>>>(x, ln1g, ln1b, xn);

    // 2) QKV per-head GEMMs (z = head)
    {
        dim3 grid(AA / 128, M / 128, HH);
        long long sBq = (long long)DD * AA;
        long long sCq = (long long)M * AA;
        gemm_nn_pipe<0><<<grid, 256, NN_SMEM>>>(xn, wq, q, nullptr, nullptr, M, AA, DD, 0, sBq, sCq);
        gemm_nn_pipe<0><<<grid, 256, NN_SMEM>>>(xn, wk, k, nullptr, nullptr, M, AA, DD, 0, sBq, sCq);
        gemm_nn_pipe<0><<<grid, 256, NN_SMEM>>>(xn, wv, v, nullptr, nullptr, M, AA, DD, 0, sBq, sCq);
    }

    // 3) s = q @ k^T (64 batches)
    {
        dim3 grid(LL / 128, LL / 128, HH * BB);
        long long st = (long long)LL * AA;
        gemm_bt<132><<<grid, 256>>>(q, k, s, LL, LL, AA, st, st, st);
    }

    // 4) column softmax + p*v^T + concat (att tf32-rounded)
    {
        dim3 grid(LL / 32, HH * BB);
        dim3 blk(32, 16);
        softmax_att_kernel<<<grid, blk>>>(s, v, att);
    }

    // 5) x1 = x + att @ fc_w + fc_b
    {
        dim3 grid(DD / 128, M / 128, 1);
        gemm_nn_pipe<1><<<grid, 256, NN_SMEM>>>(att, wfc, x1, fc_b, x, M, DD, DD, 0, 0, 0);
    }

    // 6) ln2 (output tf32-rounded)
    ln_kernel<<<M, 256>>>(x1, ln2g, ln2b, xn);

    // 7) h = gelu(xn @ W1 + b1)  (output tf32-rounded)
    {
        dim3 grid(FF / 128, M / 128, 1);
        gemm_nn_pipe<2><<<grid, 256, NN_SMEM>>>(xn, w1, hb, b1, nullptr, M, FF, DD, 0, 0, 0);
    }

    // 8) out = x1 + h @ W2 + b2
    {
        dim3 grid(DD / 128, M / 128, 1);
        gemm_nn_pipe<1><<<grid, 256, NN_SMEM>>>(hb, w2, out, b2, x1, M, DD, FF, 0, 0, 0);
    }
}

// round 4
// speedup vs baseline: 1.4193x; 1.0184x over previous
#include <cuda_runtime.h>
#include <cstdint>
#include <math.h>

#define BB 8
#define LL 512
#define DD 4096
#define HH 8
#define FF 16384
#define AA 512   // per-head dim == L

// ---------------- scratch (device globals: allocation-free) ----------------
__device__ float g_xn [BB*LL*DD];
__device__ float g_q  [HH*BB*LL*AA];
__device__ float g_k  [HH*BB*LL*AA];
__device__ float g_v  [HH*BB*LL*AA];
__device__ float g_s  [HH*BB*LL*LL];
__device__ float g_att[BB*LL*DD];
__device__ float g_x1 [BB*LL*DD];
__device__ float g_h  [BB*LL*FF];
// tf32-rounded weight copies
__device__ float g_wq [HH*DD*AA];
__device__ float g_wk [HH*DD*AA];
__device__ float g_wv [HH*DD*AA];
__device__ float g_wfc[DD*DD];
__device__ float g_w1 [DD*FF];
__device__ float g_w2 [FF*DD];

// ---------------- helpers ----------------
__device__ __forceinline__ uint32_t f2tf(float f) {
    uint32_t r;
    asm("cvt.rna.tf32.f32 %0, %1;" : "=r"(r) : "f"(f));
    return r;
}
__device__ __forceinline__ float roundtf(float f) {
    return __uint_as_float(f2tf(f));
}
__device__ __forceinline__ float gelu_exact(float x) {
    return 0.5f * x * (1.0f + erff(x * 0.7071067811865475f));
}
__device__ __forceinline__ uint32_t sptr(const void* p) {
    return (uint32_t)__cvta_generic_to_shared(p);
}
__device__ __forceinline__ void cp16(void* dst, const void* src) {
    asm volatile("cp.async.cg.shared.global [%0], [%1], 16;" :: "r"(sptr(dst)), "l"(src));
}
__device__ __forceinline__ void cp_commit() {
    asm volatile("cp.async.commit_group;");
}
__device__ __forceinline__ void cp_wait1() {
    asm volatile("cp.async.wait_group 1;");
}

// ---------------- tf32 rounding pass (weights) ----------------
__global__ void round_tf32_kernel(const float4* __restrict__ in,
                                  float4* __restrict__ out, int n4)
{
    int i = blockIdx.x * blockDim.x + threadIdx.x;
    if (i < n4) {
        float4 v = in[i];
        v.x = roundtf(v.x); v.y = roundtf(v.y);
        v.z = roundtf(v.z); v.w = roundtf(v.w);
        out[i] = v;
    }
}

// ---------------- layernorm (output rounded to tf32) ----------------
__global__ void ln_kernel(const float* __restrict__ x,
                          const float* __restrict__ g,
                          const float* __restrict__ b,
                          float* __restrict__ out)
{
    int row = blockIdx.x;
    const float4* xr = (const float4*)(x + (size_t)row * DD);
    __shared__ float red[256];
    float4 vals[4];
    float s = 0.f;
#pragma unroll
    for (int it = 0; it < 4; ++it) {
        float4 v = xr[threadIdx.x + it * 256];
        vals[it] = v;
        s += v.x + v.y + v.z + v.w;
    }
    red[threadIdx.x] = s; __syncthreads();
    for (int st = 128; st > 0; st >>= 1) {
        if (threadIdx.x < st) red[threadIdx.x] += red[threadIdx.x + st];
        __syncthreads();
    }
    float mean = red[0] * (1.f / DD);
    __syncthreads();
    float vs = 0.f;
#pragma unroll
    for (int it = 0; it < 4; ++it) {
        float4 v = vals[it];
        float dx = v.x - mean, dy = v.y - mean, dz = v.z - mean, dw = v.w - mean;
        vs += dx*dx + dy*dy + dz*dz + dw*dw;
    }
    red[threadIdx.x] = vs; __syncthreads();
    for (int st = 128; st > 0; st >>= 1) {
        if (threadIdx.x < st) red[threadIdx.x] += red[threadIdx.x + st];
        __syncthreads();
    }
    float rstd = rsqrtf(red[0] * (1.f / DD) + 1e-5f);
    float4* o = (float4*)(out + (size_t)row * DD);
#pragma unroll
    for (int it = 0; it < 4; ++it) {
        int c = (threadIdx.x + it * 256) * 4;
        float4 v = vals[it];
        float4 gg = *(const float4*)(g + c);
        float4 bb = *(const float4*)(b + c);
        float4 r;
        r.x = roundtf((v.x - mean) * rstd * gg.x + bb.x);
        r.y = roundtf((v.y - mean) * rstd * gg.y + bb.y);
        r.z = roundtf((v.z - mean) * rstd * gg.z + bb.z);
        r.w = roundtf((v.w - mean) * rstd * gg.w + bb.w);
        o[threadIdx.x + it * 256] = r;
    }
}

// =====================================================================
// Pipelined NN tf32 GEMM. Operands PRE-ROUNDED tf32 in gmem.
// 128x128x32 CTA tile, 128 threads, 4 warps of 64x64 (2x2 warp grid).
// 2-stage cp.async. EPI: 0 none, 1 bias+res, 2 bias+gelu
// =====================================================================
#define LDAS 36
#define LDBS 136
#define A_TILE (128 * LDAS)
#define B_TILE (32 * LDBS)
#define NN_SMEM ((2 * (A_TILE + B_TILE)) * 4)

template<int EPI>
__global__ void __launch_bounds__(128, 2)
gemm_nn_pipe(const float* __restrict__ A, const float* __restrict__ B,
             float* __restrict__ C, const float* __restrict__ bias,
             const float* __restrict__ res,
             int M, int N, int K,
             long long sA, long long sB, long long sC)
{
    extern __shared__ float smem[];
    float* As = smem;
    float* Bs = smem + 2 * A_TILE;

    int z = blockIdx.z;
    A += (long long)z * sA;
    B += (long long)z * sB;
    C += (long long)z * sC;

    int m0 = blockIdx.y * 128, n0 = blockIdx.x * 128;
    int tid = threadIdx.x;
    int warp = tid >> 5, lane = tid & 31;
    int wm = (warp >> 1) * 64, wn = (warp & 1) * 64;
    int gid = lane >> 2, tig = lane & 3;

    // loaders: 128 threads, 8 float4 each for A (128x32) and B (32x128)
    int a_rm = tid >> 3, a_c4 = (tid & 7) * 4;          // rows step 16 per iter
    int b_rk = tid >> 5, b_c4 = (tid & 31) * 4;         // rows step 4 per iter

    float acc[4][8][4];
#pragma unroll
    for (int a = 0; a < 4; ++a)
#pragma unroll
        for (int b = 0; b < 8; ++b)
#pragma unroll
            for (int c = 0; c < 4; ++c) acc[a][b][c] = 0.f;

    const int kTiles = K >> 5;

    {
        const float* Ag = A + (size_t)(m0 + a_rm) * K + a_c4;
        const float* Bg = B + (size_t)b_rk * N + n0 + b_c4;
        float* Ad = As + a_rm * LDAS + a_c4;
        float* Bd = Bs + b_rk * LDBS + b_c4;
#pragma unroll
        for (int it = 0; it < 8; ++it) {
            cp16(Ad + it * 16 * LDAS, Ag + (size_t)it * 16 * K);
            cp16(Bd + it * 4 * LDBS, Bg + (size_t)it * 4 * N);
        }
    }
    cp_commit();

    for (int t = 0; t < kTiles; ++t) {
        if (t + 1 < kTiles) {
            int kt = (t + 1) << 5;
            int st = (t + 1) & 1;
            const float* Ag = A + (size_t)(m0 + a_rm) * K + kt + a_c4;
            const float* Bg = B + (size_t)(kt + b_rk) * N + n0 + b_c4;
            float* Ad = As + st * A_TILE + a_rm * LDAS + a_c4;
            float* Bd = Bs + st * B_TILE + b_rk * LDBS + b_c4;
#pragma unroll
            for (int it = 0; it < 8; ++it) {
                cp16(Ad + it * 16 * LDAS, Ag + (size_t)it * 16 * K);
                cp16(Bd + it * 4 * LDBS, Bg + (size_t)it * 4 * N);
            }
        }
        cp_commit();
        cp_wait1();
        __syncthreads();

        const float* As_s = As + (t & 1) * A_TILE;
        const float* Bs_s = Bs + (t & 1) * B_TILE;

#pragma unroll
        for (int ks = 0; ks < 4; ++ks) {
            uint32_t af[4][4], bf[8][2];
#pragma unroll
            for (int mf = 0; mf < 4; ++mf) {
                const float* p = &As_s[(wm + mf * 16 + gid) * LDAS + ks * 8 + tig];
                af[mf][0] = __float_as_uint(p[0]);
                af[mf][1] = __float_as_uint(p[8 * LDAS]);
                af[mf][2] = __float_as_uint(p[4]);
                af[mf][3] = __float_as_uint(p[8 * LDAS + 4]);
            }
#pragma unroll
            for (int nf = 0; nf < 8; ++nf) {
                const float* p = &Bs_s[(ks * 8 + tig) * LDBS + wn + nf * 8 + gid];
                bf[nf][0] = __float_as_uint(p[0]);
                bf[nf][1] = __float_as_uint(p[4 * LDBS]);
            }
#pragma unroll
            for (int mf = 0; mf < 4; ++mf)
#pragma unroll
                for (int nf = 0; nf < 8; ++nf) {
                    asm volatile(
                        "mma.sync.aligned.m16n8k8.row.col.f32.tf32.tf32.f32 "
                        "{%0,%1,%2,%3}, {%4,%5,%6,%7}, {%8,%9}, {%0,%1,%2,%3};"
                        : "+f"(acc[mf][nf][0]), "+f"(acc[mf][nf][1]),
                          "+f"(acc[mf][nf][2]), "+f"(acc[mf][nf][3])
                        : "r"(af[mf][0]), "r"(af[mf][1]), "r"(af[mf][2]), "r"(af[mf][3]),
                          "r"(bf[nf][0]), "r"(bf[nf][1]));
                }
        }
        __syncthreads();
    }

#pragma unroll
    for (int mf = 0; mf < 4; ++mf) {
        int r0 = m0 + wm + mf * 16 + gid;
#pragma unroll
        for (int nf = 0; nf < 8; ++nf) {
            int c = n0 + wn + nf * 8 + tig * 2;
#pragma unroll
            for (int half = 0; half < 2; ++half) {
                int r = r0 + half * 8;
                float v0 = acc[mf][nf][half * 2 + 0];
                float v1 = acc[mf][nf][half * 2 + 1];
                if (EPI >= 1) { v0 += bias[c]; v1 += bias[c + 1]; }
                if (EPI == 2) {
                    v0 = roundtf(gelu_exact(v0));
                    v1 = roundtf(gelu_exact(v1));
                }
                size_t off = (size_t)r * N + c;
                if (EPI == 1) { v0 += res[off]; v1 += res[off + 1]; }
                *(float2*)(C + off) = make_float2(v0, v1);
            }
        }
    }
}

// =====================================================================
// Synchronous BT GEMM (A @ B^T) — only for S = Q K^T (1% of FLOPs)
// 256 threads, 8 warps of 64x32
// =====================================================================
template<int LDBT>
__global__ void __launch_bounds__(256, 2)
gemm_bt(const float* __restrict__ A, const float* __restrict__ B,
        float* __restrict__ C,
        int M, int N, int K,
        long long sA, long long sB, long long sC)
{
    __shared__ uint32_t As[128 * LDAS];
    __shared__ uint32_t Bs[32 * LDBT];

    int z = blockIdx.z;
    A += (long long)z * sA;
    B += (long long)z * sB;
    C += (long long)z * sC;

    int m0 = blockIdx.y * 128, n0 = blockIdx.x * 128;
    int tid = threadIdx.x;
    int warp = tid >> 5, lane = tid & 31;
    int wm = (warp >> 2) * 64, wn = (warp & 3) * 32;
    int gid = lane >> 2, tig = lane & 3;

    float acc[4][4][4];
#pragma unroll
    for (int a = 0; a < 4; ++a)
#pragma unroll
        for (int b = 0; b < 4; ++b)
#pragma unroll
            for (int c = 0; c < 4; ++c) acc[a][b][c] = 0.f;

    for (int kt = 0; kt < K; kt += 32) {
#pragma unroll
        for (int it = 0; it < 4; ++it) {
            int idx = tid + it * 256;
            int rm = idx >> 3, c4 = idx & 7;
            float4 v = *(const float4*)(A + (size_t)(m0 + rm) * K + kt + c4 * 4);
            uint32_t* dst = &As[rm * LDAS + c4 * 4];
            dst[0] = __float_as_uint(v.x); dst[1] = __float_as_uint(v.y);
            dst[2] = __float_as_uint(v.z); dst[3] = __float_as_uint(v.w);
        }
#pragma unroll
        for (int it = 0; it < 4; ++it) {
            int idx = tid + it * 256;
            int rn = idx >> 3, c4 = idx & 7;
            float4 v = *(const float4*)(B + (size_t)(n0 + rn) * K + kt + c4 * 4);
            Bs[(c4 * 4 + 0) * LDBT + rn] = __float_as_uint(v.x);
            Bs[(c4 * 4 + 1) * LDBT + rn] = __float_as_uint(v.y);
            Bs[(c4 * 4 + 2) * LDBT + rn] = __float_as_uint(v.z);
            Bs[(c4 * 4 + 3) * LDBT + rn] = __float_as_uint(v.w);
        }
        __syncthreads();

#pragma unroll
        for (int ks = 0; ks < 4; ++ks) {
            uint32_t af[4][4], bf[4][2];
#pragma unroll
            for (int mf = 0; mf < 4; ++mf) {
                const uint32_t* p = &As[(wm + mf * 16 + gid) * LDAS + ks * 8 + tig];
                af[mf][0] = p[0];
                af[mf][1] = p[8 * LDAS];
                af[mf][2] = p[4];
                af[mf][3] = p[8 * LDAS + 4];
            }
#pragma unroll
            for (int nf = 0; nf < 4; ++nf) {
                const uint32_t* p = &Bs[(ks * 8 + tig) * LDBT + wn + nf * 8 + gid];
                bf[nf][0] = p[0];
                bf[nf][1] = p[4 * LDBT];
            }
#pragma unroll
            for (int mf = 0; mf < 4; ++mf)
#pragma unroll
                for (int nf = 0; nf < 4; ++nf) {
                    asm volatile(
                        "mma.sync.aligned.m16n8k8.row.col.f32.tf32.tf32.f32 "
                        "{%0,%1,%2,%3}, {%4,%5,%6,%7}, {%8,%9}, {%0,%1,%2,%3};"
                        : "+f"(acc[mf][nf][0]), "+f"(acc[mf][nf][1]),
                          "+f"(acc[mf][nf][2]), "+f"(acc[mf][nf][3])
                        : "r"(af[mf][0]), "r"(af[mf][1]), "r"(af[mf][2]), "r"(af[mf][3]),
                          "r"(bf[nf][0]), "r"(bf[nf][1]));
                }
        }
        __syncthreads();
    }

#pragma unroll
    for (int mf = 0; mf < 4; ++mf) {
        int r0 = m0 + wm + mf * 16 + gid;
#pragma unroll
        for (int nf = 0; nf < 4; ++nf) {
            int c = n0 + wn + nf * 8 + tig * 2;
#pragma unroll
            for (int half = 0; half < 2; ++half) {
                int r = r0 + half * 8;
                size_t off = (size_t)r * N + c;
                *(float2*)(C + off) = make_float2(acc[mf][nf][half * 2 + 0],
                                                  acc[mf][nf][half * 2 + 1]);
            }
        }
    }
}

// ---------------- column softmax + p * v^T + head concat (att rounded) ----------------
__global__ void softmax_att_kernel(const float* __restrict__ s,
                                   const float* __restrict__ v,
                                   float* __restrict__ att)
{
    int z = blockIdx.y;          // z = h*B + b
    int h = z >> 3, b = z & 7;
    int j0 = blockIdx.x * 32;
    int tx = threadIdx.x, ty = threadIdx.y;   // 32 x 16
    const float* sp = s + (size_t)z * LL * LL;
    const float rs = 0.04419417382415922f;    // 1/sqrt(512)
    int j = j0 + tx;

    float part = 0.f;
    for (int it = 0; it < 32; ++it) {
        int i = it * 16 + ty;
        float val = (j <= i) ? sp[(size_t)i * LL + j] : -1000.f;
        part += expf(val * rs);
    }
    __shared__ float red[16][32];
    __shared__ float cinv[32];
    red[ty][tx] = part; __syncthreads();
    if (ty < 8) red[ty][tx] += red[ty + 8][tx];
    __syncthreads();
    if (ty < 4) red[ty][tx] += red[ty + 4][tx];
    __syncthreads();
    if (ty < 2) red[ty][tx] += red[ty + 2][tx];
    __syncthreads();
    if (ty == 0) cinv[tx] = 1.f / (red[0][tx] + red[1][tx]);
    __syncthreads();
    float ci = cinv[tx];

    __shared__ float vt[32][17];
    const float* vp = v + ((size_t)z * LL + j0) * AA;
    size_t attbase = (size_t)b * LL * DD + (size_t)h * AA + j0;
    int tid = ty * 32 + tx;
    int vr = tid >> 4, vc = tid & 15;
    for (int it = 0; it < 32; ++it) {
        __syncthreads();
        vt[vr][vc] = vp[(size_t)vr * AA + it * 16 + vc];
        __syncthreads();
        int i = it * 16 + ty;
        float val = (j <= i) ? sp[(size_t)i * LL + j] : -1000.f;
        float p = expf(val * rs) * ci;
        att[attbase + (size_t)i * DD + tx] = roundtf(p * vt[tx][ty]);
    }
}

// ---------------- launch ----------------
extern "C" void kernel_launch(void* const* d_in, const int* in_sizes, int n_in,
                              void* d_out, int out_size)
{
    (void)in_sizes; (void)n_in; (void)out_size;
    const float* x    = (const float*)d_in[0];
    const float* Wq   = (const float*)d_in[2];
    const float* Wk   = (const float*)d_in[3];
    const float* Wv   = (const float*)d_in[4];
    const float* fc_w = (const float*)d_in[5];
    const float* fc_b = (const float*)d_in[6];
    const float* ln1g = (const float*)d_in[7];
    const float* ln1b = (const float*)d_in[8];
    const float* W1   = (const float*)d_in[9];
    const float* b1   = (const float*)d_in[10];
    const float* W2   = (const float*)d_in[11];
    const float* b2   = (const float*)d_in[12];
    const float* ln2g = (const float*)d_in[13];
    const float* ln2b = (const float*)d_in[14];
    float* out = (float*)d_out;

    float *xn, *q, *k, *v, *s, *att, *x1, *hb;
    float *wq, *wk, *wv, *wfc, *w1, *w2;
    cudaGetSymbolAddress((void**)&xn,  g_xn);
    cudaGetSymbolAddress((void**)&q,   g_q);
    cudaGetSymbolAddress((void**)&k,   g_k);
    cudaGetSymbolAddress((void**)&v,   g_v);
    cudaGetSymbolAddress((void**)&s,   g_s);
    cudaGetSymbolAddress((void**)&att, g_att);
    cudaGetSymbolAddress((void**)&x1,  g_x1);
    cudaGetSymbolAddress((void**)&hb,  g_h);
    cudaGetSymbolAddress((void**)&wq,  g_wq);
    cudaGetSymbolAddress((void**)&wk,  g_wk);
    cudaGetSymbolAddress((void**)&wv,  g_wv);
    cudaGetSymbolAddress((void**)&wfc, g_wfc);
    cudaGetSymbolAddress((void**)&w1,  g_w1);
    cudaGetSymbolAddress((void**)&w2,  g_w2);

    cudaFuncSetAttribute(gemm_nn_pipe<0>, cudaFuncAttributeMaxDynamicSharedMemorySize, NN_SMEM);
    cudaFuncSetAttribute(gemm_nn_pipe<1>, cudaFuncAttributeMaxDynamicSharedMemorySize, NN_SMEM);
    cudaFuncSetAttribute(gemm_nn_pipe<2>, cudaFuncAttributeMaxDynamicSharedMemorySize, NN_SMEM);

    const int M = BB * LL;   // 4096

    // 0) tf32-round weights into scratch copies
    {
        int t = 256;
        int nqkv = HH * DD * AA / 4;
        round_tf32_kernel<<<nqkv / t, t>>>((const float4*)Wq, (float4*)wq, nqkv);
        round_tf32_kernel<<<nqkv / t, t>>>((const float4*)Wk, (float4*)wk, nqkv);
        round_tf32_kernel<<<nqkv / t, t>>>((const float4*)Wv, (float4*)wv, nqkv);
        int nfc = DD * DD / 4;
        round_tf32_kernel<<<nfc / t, t>>>((const float4*)fc_w, (float4*)wfc, nfc);
        int nw1 = DD * FF / 4;
        round_tf32_kernel<<<nw1 / t, t>>>((const float4*)W1, (float4*)w1, nw1);
        round_tf32_kernel<<<nw1 / t, t>>>((const float4*)W2, (float4*)w2, nw1);
    }

    // 1) ln1 (output tf32-rounded)
    ln_kernel<<<M, 256>>>(x, ln1g, ln1b, xn);

    // 2) QKV per-head GEMMs (z = head)
    {
        dim3 grid(AA / 128, M / 128, HH);
        long long sBq = (long long)DD * AA;
        long long sCq = (long long)M * AA;
        gemm_nn_pipe<0><<<grid, 128, NN_SMEM>>>(xn, wq, q, nullptr, nullptr, M, AA, DD, 0, sBq, sCq);
        gemm_nn_pipe<0><<<grid, 128, NN_SMEM>>>(xn, wk, k, nullptr, nullptr, M, AA, DD, 0, sBq, sCq);
        gemm_nn_pipe<0><<<grid, 128, NN_SMEM>>>(xn, wv, v, nullptr, nullptr, M, AA, DD, 0, sBq, sCq);
    }

    // 3) s = q @ k^T (64 batches; q/k already tf32-rounded via tf32 mma outputs? q,k are
    //    fp32 accumulators — round happens inside gemm_bt loads? No: keep exact behavior:
    //    q,k are fp32; gemm_bt now reads raw bits, so round q,k first? They were produced
    //    by tf32 mma with fp32 accum — NOT tf32-clean. Round via f2tf in the BT loader was
    //    removed, so restore equivalence by rounding here:
    {
        int t = 256;
        int nqk = HH * BB * LL * AA / 4;
        round_tf32_kernel<<<nqk / t, t>>>((const float4*)q, (float4*)q, nqk);
        round_tf32_kernel<<<nqk / t, t>>>((const float4*)k, (float4*)k, nqk);
    }
    {
        dim3 grid(LL / 128, LL / 128, HH * BB);
        long long st = (long long)LL * AA;
        gemm_bt<132><<<grid, 256>>>(q, k, s, LL, LL, AA, st, st, st);
    }

    // 4) column softmax + p*v^T + concat (att tf32-rounded)
    {
        dim3 grid(LL / 32, HH * BB);
        dim3 blk(32, 16);
        softmax_att_kernel<<<grid, blk>>>(s, v, att);
    }

    // 5) x1 = x + att @ fc_w + fc_b
    {
        dim3 grid(DD / 128, M / 128, 1);
        gemm_nn_pipe<1><<<grid, 128, NN_SMEM>>>(att, wfc, x1, fc_b, x, M, DD, DD, 0, 0, 0);
    }

    // 6) ln2 (output tf32-rounded)
    ln_kernel<<<M, 256>>>(x1, ln2g, ln2b, xn);

    // 7) h = gelu(xn @ W1 + b1)  (output tf32-rounded)
    {
        dim3 grid(FF / 128, M / 128, 1);
        gemm_nn_pipe<2><<<grid, 128, NN_SMEM>>>(xn, w1, hb, b1, nullptr, M, FF, DD, 0, 0, 0);
    }

    // 8) out = x1 + h @ W2 + b2
    {
        dim3 grid(DD / 128, M / 128, 1);
        gemm_nn_pipe<1><<<grid, 128, NN_SMEM>>>(hb, w2, out, b2, x1, M, DD, FF, 0, 0, 0);
    }
}

// round 6
// speedup vs baseline: 1.4553x; 1.0254x over previous
#include <cuda_runtime.h>
#include <cstdint>
#include <math.h>

#define BB 8
#define LL 512
#define DD 4096
#define HH 8
#define FF 16384
#define AA 512   // per-head dim == L

// ---------------- scratch (device globals: allocation-free) ----------------
__device__ float g_xn  [BB*LL*DD];
__device__ float g_qkv [3*HH*BB*LL*AA];   // [which][head][B*L][A]
__device__ float g_s   [HH*BB*LL*LL];     // (H,B,L,L)
__device__ float g_att [BB*LL*DD];
__device__ float g_x1  [BB*LL*DD];
__device__ float g_h   [BB*LL*FF];
// tf32-rounded weights
__device__ float g_wqkv[3*HH*DD*AA];      // [which][head][D][A]
__device__ float g_wfc [DD*DD];
__device__ float g_w1  [DD*FF];
__device__ float g_w2  [FF*DD];

// ---------------- helpers ----------------
__device__ __forceinline__ uint32_t f2tf(float f) {
    uint32_t r;
    asm("cvt.rna.tf32.f32 %0, %1;" : "=r"(r) : "f"(f));
    return r;
}
__device__ __forceinline__ float roundtf(float f) {
    return __uint_as_float(f2tf(f));
}
__device__ __forceinline__ float gelu_exact(float x) {
    return 0.5f * x * (1.0f + erff(x * 0.7071067811865475f));
}
__device__ __forceinline__ uint32_t sptr(const void* p) {
    return (uint32_t)__cvta_generic_to_shared(p);
}
__device__ __forceinline__ void cp16(void* dst, const void* src) {
    asm volatile("cp.async.cg.shared.global [%0], [%1], 16;" :: "r"(sptr(dst)), "l"(src));
}
__device__ __forceinline__ void cp_commit() {
    asm volatile("cp.async.commit_group;");
}
template<int N>
__device__ __forceinline__ void cp_wait() {
    asm volatile("cp.async.wait_group %0;" :: "n"(N));
}

// ---------------- fused weight prep: tf32-round all weights, 1 launch ----------------
#define NQKV4 (HH*DD*AA/4)         // 4,194,304 float4 per matrix
#define NFC4  (DD*DD/4)            // 4,194,304
#define NW4   (DD*FF/4)            // 16,777,216
#define PREP_TOTAL (3*NQKV4 + NFC4 + 2*NW4)   // 50,331,648

__device__ __forceinline__ float4 round4(float4 v) {
    v.x = roundtf(v.x); v.y = roundtf(v.y);
    v.z = roundtf(v.z); v.w = roundtf(v.w);
    return v;
}

__global__ void prep_weights(const float4* __restrict__ Wq, const float4* __restrict__ Wk,
                             const float4* __restrict__ Wv, const float4* __restrict__ Wfc,
                             const float4* __restrict__ W1, const float4* __restrict__ W2,
                             float4* __restrict__ wqkv, float4* __restrict__ wfc,
                             float4* __restrict__ w1, float4* __restrict__ w2)
{
    long long i = (long long)blockIdx.x * blockDim.x + threadIdx.x;
    if (i < 3LL * NQKV4) {
        int w = (int)(i >> 22);           // / 4,194,304
        int r = (int)(i & (NQKV4 - 1));
        const float4* src = (w == 0) ? Wq : (w == 1) ? Wk : Wv;
        wqkv[i] = round4(src[r]);
    } else if (i < 3LL * NQKV4 + NFC4) {
        long long r = i - 3LL * NQKV4;
        wfc[r] = round4(Wfc[r]);
    } else if (i < 3LL * NQKV4 + NFC4 + NW4) {
        long long r = i - (3LL * NQKV4 + NFC4);
        w1[r] = round4(W1[r]);
    } else {
        long long r = i - (3LL * NQKV4 + NFC4 + NW4);
        w2[r] = round4(W2[r]);
    }
}

// ---------------- layernorm (output tf32-rounded) ----------------
__global__ void ln_kernel(const float* __restrict__ x,
                          const float* __restrict__ g,
                          const float* __restrict__ b,
                          float* __restrict__ out)
{
    int row = blockIdx.x;
    const float4* xr = (const float4*)(x + (size_t)row * DD);
    __shared__ float red[256];
    float4 vals[4];
    float s = 0.f;
#pragma unroll
    for (int it = 0; it < 4; ++it) {
        float4 v = xr[threadIdx.x + it * 256];
        vals[it] = v;
        s += v.x + v.y + v.z + v.w;
    }
    red[threadIdx.x] = s; __syncthreads();
    for (int st = 128; st > 0; st >>= 1) {
        if (threadIdx.x < st) red[threadIdx.x] += red[threadIdx.x + st];
        __syncthreads();
    }
    float mean = red[0] * (1.f / DD);
    __syncthreads();
    float vs = 0.f;
#pragma unroll
    for (int it = 0; it < 4; ++it) {
        float4 v = vals[it];
        float dx = v.x - mean, dy = v.y - mean, dz = v.z - mean, dw = v.w - mean;
        vs += dx*dx + dy*dy + dz*dz + dw*dw;
    }
    red[threadIdx.x] = vs; __syncthreads();
    for (int st = 128; st > 0; st >>= 1) {
        if (threadIdx.x < st) red[threadIdx.x] += red[threadIdx.x + st];
        __syncthreads();
    }
    float rstd = rsqrtf(red[0] * (1.f / DD) + 1e-5f);
    float4* o = (float4*)(out + (size_t)row * DD);
#pragma unroll
    for (int it = 0; it < 4; ++it) {
        int c = (threadIdx.x + it * 256) * 4;
        float4 v = vals[it];
        float4 gg = *(const float4*)(g + c);
        float4 bb = *(const float4*)(b + c);
        float4 r;
        r.x = roundtf((v.x - mean) * rstd * gg.x + bb.x);
        r.y = roundtf((v.y - mean) * rstd * gg.y + bb.y);
        r.z = roundtf((v.z - mean) * rstd * gg.z + bb.z);
        r.w = roundtf((v.w - mean) * rstd * gg.w + bb.w);
        o[threadIdx.x + it * 256] = r;
    }
}

// =====================================================================
// 3-stage pipelined NN tf32 GEMM. Operands PRE-ROUNDED tf32 in gmem.
// 128x128x32 CTA tile, 128 threads, 4 warps of 64x64.
// ONE __syncthreads per k-tile.
// EPI: 0 raw, 1 bias+res, 2 bias+gelu+round, 3 round
// =====================================================================
#define LDAS 36
#define LDBS 136
#define A_TILE (128 * LDAS)
#define B_TILE (32 * LDBS)
#define NSTG 3
#define NN_SMEM (NSTG * (A_TILE + B_TILE) * 4)

template<int EPI>
__global__ void __launch_bounds__(128, 2)
gemm_nn_pipe(const float* __restrict__ A, const float* __restrict__ B,
             float* __restrict__ C, const float* __restrict__ bias,
             const float* __restrict__ res,
             int M, int N, int K,
             long long sA, long long sB, long long sC)
{
    extern __shared__ float smem[];

    int z = blockIdx.z;
    A += (long long)z * sA;
    B += (long long)z * sB;
    C += (long long)z * sC;

    int m0 = blockIdx.y * 128, n0 = blockIdx.x * 128;
    int tid = threadIdx.x;
    int warp = tid >> 5, lane = tid & 31;
    int wm = (warp >> 1) * 64, wn = (warp & 1) * 64;
    int gid = lane >> 2, tig = lane & 3;

    int a_rm = tid >> 3, a_c4 = (tid & 7) * 4;
    int b_rk = tid >> 5, b_c4 = (tid & 31) * 4;

    float acc[4][8][4];
#pragma unroll
    for (int a = 0; a < 4; ++a)
#pragma unroll
        for (int b = 0; b < 8; ++b)
#pragma unroll
            for (int c = 0; c < 4; ++c) acc[a][b][c] = 0.f;

    const int kTiles = K >> 5;

    auto load_tile = [&](int t, int st) {
        float* As = smem + st * (A_TILE + B_TILE);
        float* Bs = As + A_TILE;
        const float* Ag = A + (size_t)(m0 + a_rm) * K + t * 32 + a_c4;
        const float* Bg = B + (size_t)(t * 32 + b_rk) * N + n0 + b_c4;
        float* Ad = As + a_rm * LDAS + a_c4;
        float* Bd = Bs + b_rk * LDBS + b_c4;
#pragma unroll
        for (int it = 0; it < 8; ++it) {
            cp16(Ad + it * 16 * LDAS, Ag + (size_t)it * 16 * K);
            cp16(Bd + it * 4 * LDBS, Bg + (size_t)it * 4 * N);
        }
    };

    load_tile(0, 0);
    cp_commit();
    if (kTiles > 1) load_tile(1, 1);
    cp_commit();

    int st = 0;
    for (int t = 0; t < kTiles; ++t) {
        cp_wait<1>();
        __syncthreads();
        int st2 = st + 2; if (st2 >= NSTG) st2 -= NSTG;
        if (t + 2 < kTiles) load_tile(t + 2, st2);
        cp_commit();

        const float* As_s = smem + st * (A_TILE + B_TILE);
        const float* Bs_s = As_s + A_TILE;

#pragma unroll
        for (int ks = 0; ks < 4; ++ks) {
            uint32_t af[4][4], bf[8][2];
#pragma unroll
            for (int mf = 0; mf < 4; ++mf) {
                const float* p = &As_s[(wm + mf * 16 + gid) * LDAS + ks * 8 + tig];
                af[mf][0] = __float_as_uint(p[0]);
                af[mf][1] = __float_as_uint(p[8 * LDAS]);
                af[mf][2] = __float_as_uint(p[4]);
                af[mf][3] = __float_as_uint(p[8 * LDAS + 4]);
            }
#pragma unroll
            for (int nf = 0; nf < 8; ++nf) {
                const float* p = &Bs_s[(ks * 8 + tig) * LDBS + wn + nf * 8 + gid];
                bf[nf][0] = __float_as_uint(p[0]);
                bf[nf][1] = __float_as_uint(p[4 * LDBS]);
            }
#pragma unroll
            for (int mf = 0; mf < 4; ++mf)
#pragma unroll
                for (int nf = 0; nf < 8; ++nf) {
                    asm volatile(
                        "mma.sync.aligned.m16n8k8.row.col.f32.tf32.tf32.f32 "
                        "{%0,%1,%2,%3}, {%4,%5,%6,%7}, {%8,%9}, {%0,%1,%2,%3};"
                        : "+f"(acc[mf][nf][0]), "+f"(acc[mf][nf][1]),
                          "+f"(acc[mf][nf][2]), "+f"(acc[mf][nf][3])
                        : "r"(af[mf][0]), "r"(af[mf][1]), "r"(af[mf][2]), "r"(af[mf][3]),
                          "r"(bf[nf][0]), "r"(bf[nf][1]));
                }
        }
        if (++st >= NSTG) st = 0;
    }

#pragma unroll
    for (int mf = 0; mf < 4; ++mf) {
        int r0 = m0 + wm + mf * 16 + gid;
#pragma unroll
        for (int nf = 0; nf < 8; ++nf) {
            int c = n0 + wn + nf * 8 + tig * 2;
#pragma unroll
            for (int half = 0; half < 2; ++half) {
                int r = r0 + half * 8;
                float v0 = acc[mf][nf][half * 2 + 0];
                float v1 = acc[mf][nf][half * 2 + 1];
                if (EPI == 1 || EPI == 2) { v0 += bias[c]; v1 += bias[c + 1]; }
                if (EPI == 2) {
                    v0 = roundtf(gelu_exact(v0));
                    v1 = roundtf(gelu_exact(v1));
                }
                if (EPI == 3) { v0 = roundtf(v0); v1 = roundtf(v1); }
                size_t off = (size_t)r * N + c;
                if (EPI == 1) { v0 += res[off]; v1 += res[off + 1]; }
                *(float2*)(C + off) = make_float2(v0, v1);
            }
        }
    }
}

// =====================================================================
// Synchronous BT GEMM (A @ B^T) — only for S = Q K^T (1% of FLOPs)
// inputs pre-rounded tf32
// =====================================================================
template<int LDBT>
__global__ void __launch_bounds__(256, 2)
gemm_bt(const float* __restrict__ A, const float* __restrict__ B,
        float* __restrict__ C,
        int M, int N, int K,
        long long sA, long long sB, long long sC)
{
    __shared__ uint32_t As[128 * LDAS];
    __shared__ uint32_t Bs[32 * LDBT];

    int z = blockIdx.z;
    A += (long long)z * sA;
    B += (long long)z * sB;
    C += (long long)z * sC;

    int m0 = blockIdx.y * 128, n0 = blockIdx.x * 128;
    int tid = threadIdx.x;
    int warp = tid >> 5, lane = tid & 31;
    int wm = (warp >> 2) * 64, wn = (warp & 3) * 32;
    int gid = lane >> 2, tig = lane & 3;

    float acc[4][4][4];
#pragma unroll
    for (int a = 0; a < 4; ++a)
#pragma unroll
        for (int b = 0; b < 4; ++b)
#pragma unroll
            for (int c = 0; c < 4; ++c) acc[a][b][c] = 0.f;

    for (int kt = 0; kt < K; kt += 32) {
#pragma unroll
        for (int it = 0; it < 4; ++it) {
            int idx = tid + it * 256;
            int rm = idx >> 3, c4 = idx & 7;
            float4 v = *(const float4*)(A + (size_t)(m0 + rm) * K + kt + c4 * 4);
            uint32_t* dst = &As[rm * LDAS + c4 * 4];
            dst[0] = __float_as_uint(v.x); dst[1] = __float_as_uint(v.y);
            dst[2] = __float_as_uint(v.z); dst[3] = __float_as_uint(v.w);
        }
#pragma unroll
        for (int it = 0; it < 4; ++it) {
            int idx = tid + it * 256;
            int rn = idx >> 3, c4 = idx & 7;
            float4 v = *(const float4*)(B + (size_t)(n0 + rn) * K + kt + c4 * 4);
            Bs[(c4 * 4 + 0) * LDBT + rn] = __float_as_uint(v.x);
            Bs[(c4 * 4 + 1) * LDBT + rn] = __float_as_uint(v.y);
            Bs[(c4 * 4 + 2) * LDBT + rn] = __float_as_uint(v.z);
            Bs[(c4 * 4 + 3) * LDBT + rn] = __float_as_uint(v.w);
        }
        __syncthreads();

#pragma unroll
        for (int ks = 0; ks < 4; ++ks) {
            uint32_t af[4][4], bf[4][2];
#pragma unroll
            for (int mf = 0; mf < 4; ++mf) {
                const uint32_t* p = &As[(wm + mf * 16 + gid) * LDAS + ks * 8 + tig];
                af[mf][0] = p[0];
                af[mf][1] = p[8 * LDAS];
                af[mf][2] = p[4];
                af[mf][3] = p[8 * LDAS + 4];
            }
#pragma unroll
            for (int nf = 0; nf < 4; ++nf) {
                const uint32_t* p = &Bs[(ks * 8 + tig) * LDBT + wn + nf * 8 + gid];
                bf[nf][0] = p[0];
                bf[nf][1] = p[4 * LDBT];
            }
#pragma unroll
            for (int mf = 0; mf < 4; ++mf)
#pragma unroll
                for (int nf = 0; nf < 4; ++nf) {
                    asm volatile(
                        "mma.sync.aligned.m16n8k8.row.col.f32.tf32.tf32.f32 "
                        "{%0,%1,%2,%3}, {%4,%5,%6,%7}, {%8,%9}, {%0,%1,%2,%3};"
                        : "+f"(acc[mf][nf][0]), "+f"(acc[mf][nf][1]),
                          "+f"(acc[mf][nf][2]), "+f"(acc[mf][nf][3])
                        : "r"(af[mf][0]), "r"(af[mf][1]), "r"(af[mf][2]), "r"(af[mf][3]),
                          "r"(bf[nf][0]), "r"(bf[nf][1]));
                }
        }
        __syncthreads();
    }

#pragma unroll
    for (int mf = 0; mf < 4; ++mf) {
        int r0 = m0 + wm + mf * 16 + gid;
#pragma unroll
        for (int nf = 0; nf < 4; ++nf) {
            int c = n0 + wn + nf * 8 + tig * 2;
#pragma unroll
            for (int half = 0; half < 2; ++half) {
                int r = r0 + half * 8;
                size_t off = (size_t)r * N + c;
                *(float2*)(C + off) = make_float2(acc[mf][nf][half * 2 + 0],
                                                  acc[mf][nf][half * 2 + 1]);
            }
        }
    }
}

// ---------------- column softmax + p * v^T + head concat (att rounded) ----------------
__global__ void softmax_att_kernel(const float* __restrict__ s,
                                   const float* __restrict__ v,
                                   float* __restrict__ att)
{
    int z = blockIdx.y;          // z = h*B + b
    int h = z >> 3, b = z & 7;
    int j0 = blockIdx.x * 32;
    int tx = threadIdx.x, ty = threadIdx.y;   // 32 x 16
    const float* sp = s + (size_t)z * LL * LL;
    const float rs = 0.04419417382415922f;    // 1/sqrt(512)
    int j = j0 + tx;

    float part = 0.f;
    for (int it = 0; it < 32; ++it) {
        int i = it * 16 + ty;
        float val = (j <= i) ? sp[(size_t)i * LL + j] : -1000.f;
        part += expf(val * rs);
    }
    __shared__ float red[16][32];
    __shared__ float cinv[32];
    red[ty][tx] = part; __syncthreads();
    if (ty < 8) red[ty][tx] += red[ty + 8][tx];
    __syncthreads();
    if (ty < 4) red[ty][tx] += red[ty + 4][tx];
    __syncthreads();
    if (ty < 2) red[ty][tx] += red[ty + 2][tx];
    __syncthreads();
    if (ty == 0) cinv[tx] = 1.f / (red[0][tx] + red[1][tx]);
    __syncthreads();
    float ci = cinv[tx];

    __shared__ float vt[32][17];
    const float* vp = v + ((size_t)z * LL + j0) * AA;
    size_t attbase = (size_t)b * LL * DD + (size_t)h * AA + j0;
    int tid = ty * 32 + tx;
    int vr = tid >> 4, vc = tid & 15;
    for (int it = 0; it < 32; ++it) {
        __syncthreads();
        vt[vr][vc] = vp[(size_t)vr * AA + it * 16 + vc];
        __syncthreads();
        int i = it * 16 + ty;
        float val = (j <= i) ? sp[(size_t)i * LL + j] : -1000.f;
        float p = expf(val * rs) * ci;
        att[attbase + (size_t)i * DD + tx] = roundtf(p * vt[tx][ty]);
    }
}

// ---------------- launch ----------------
extern "C" void kernel_launch(void* const* d_in, const int* in_sizes, int n_in,
                              void* d_out, int out_size)
{
    (void)in_sizes; (void)n_in; (void)out_size;
    const float* x    = (const float*)d_in[0];
    const float* Wq   = (const float*)d_in[2];
    const float* Wk   = (const float*)d_in[3];
    const float* Wv   = (const float*)d_in[4];
    const float* fc_w = (const float*)d_in[5];
    const float* fc_b = (const float*)d_in[6];
    const float* ln1g = (const float*)d_in[7];
    const float* ln1b = (const float*)d_in[8];
    const float* W1   = (const float*)d_in[9];
    const float* b1   = (const float*)d_in[10];
    const float* W2   = (const float*)d_in[11];
    const float* b2   = (const float*)d_in[12];
    const float* ln2g = (const float*)d_in[13];
    const float* ln2b = (const float*)d_in[14];
    float* out = (float*)d_out;

    float *xn, *qkv, *s, *att, *x1, *hb;
    float *wqkv, *wfc, *w1, *w2;
    cudaGetSymbolAddress((void**)&xn,   g_xn);
    cudaGetSymbolAddress((void**)&qkv,  g_qkv);
    cudaGetSymbolAddress((void**)&s,    g_s);
    cudaGetSymbolAddress((void**)&att,  g_att);
    cudaGetSymbolAddress((void**)&x1,   g_x1);
    cudaGetSymbolAddress((void**)&hb,   g_h);
    cudaGetSymbolAddress((void**)&wqkv, g_wqkv);
    cudaGetSymbolAddress((void**)&wfc,  g_wfc);
    cudaGetSymbolAddress((void**)&w1,   g_w1);
    cudaGetSymbolAddress((void**)&w2,   g_w2);

    cudaFuncSetAttribute(gemm_nn_pipe<1>, cudaFuncAttributeMaxDynamicSharedMemorySize, NN_SMEM);
    cudaFuncSetAttribute(gemm_nn_pipe<2>, cudaFuncAttributeMaxDynamicSharedMemorySize, NN_SMEM);
    cudaFuncSetAttribute(gemm_nn_pipe<3>, cudaFuncAttributeMaxDynamicSharedMemorySize, NN_SMEM);

    const int M = BB * LL;                           // 4096
    const long long HMA = (long long)HH * M * AA;    // per-"which" block in qkv

    // launch 0: ln1 (independent of weight prep)
    ln_kernel<<<M, 256>>>(x, ln1g, ln1b, xn);

    // launch 1: fused weight tf32-round (1 launch)
    prep_weights<<<PREP_TOTAL / 256, 256>>>(
        (const float4*)Wq, (const float4*)Wk, (const float4*)Wv,
        (const float4*)fc_w, (const float4*)W1, (const float4*)W2,
        (float4*)wqkv, (float4*)wfc, (float4*)w1, (float4*)w2);

    // launch 2: QKV batched GEMM (z = which*H + head), outputs rounded (EPI=3)
    {
        dim3 grid(AA / 128, M / 128, 3 * HH);
        gemm_nn_pipe<3><<<grid, 128, NN_SMEM>>>(xn, wqkv, qkv, nullptr, nullptr,
                                                M, AA, DD,
                                                0, (long long)DD * AA, (long long)M * AA);
    }

    // launch 3: s = q @ k^T (64 batches)
    {
        dim3 grid(LL / 128, LL / 128, HH * BB);
        long long st = (long long)LL * AA;
        gemm_bt<132><<<grid, 256>>>(qkv, qkv + HMA, s, LL, LL, AA, st, st, (long long)LL * LL);
    }

    // launch 4: column softmax + p*v^T + concat
    {
        dim3 grid(LL / 32, HH * BB);
        dim3 blk(32, 16);
        softmax_att_kernel<<<grid, blk>>>(s, qkv + 2 * HMA, att);
    }

    // launch 5 (ncu target): x1 = x + att @ fc_w + fc_b
    {
        dim3 grid(DD / 128, M / 128, 1);
        gemm_nn_pipe<1><<<grid, 128, NN_SMEM>>>(att, wfc, x1, fc_b, x, M, DD, DD, 0, 0, 0);
    }

    // launch 6: ln2
    ln_kernel<<<M, 256>>>(x1, ln2g, ln2b, xn);

    // launch 7: h = gelu(xn @ W1 + b1)
    {
        dim3 grid(FF / 128, M / 128, 1);
        gemm_nn_pipe<2><<<grid, 128, NN_SMEM>>>(xn, w1, hb, b1, nullptr, M, FF, DD, 0, 0, 0);
    }

    // launch 8: out = x1 + h @ W2 + b2
    {
        dim3 grid(DD / 128, M / 128, 1);
        gemm_nn_pipe<1><<<grid, 128, NN_SMEM>>>(hb, w2, out, b2, x1, M, DD, FF, 0, 0, 0);
    }
}

// round 7
// speedup vs baseline: 1.7105x; 1.1754x over previous
#include <cuda_runtime.h>
#include <cuda_bf16.h>
#include <cstdint>
#include <math.h>

#define BB 8
#define LL 512
#define DD 4096
#define HH 8
#define FF 16384
#define AA 512   // per-head dim == L
#define MM (BB*LL)   // 4096

// ---------------- scratch (device globals: allocation-free) ----------------
__device__ __align__(16) float g_xn [MM*DD];                 // ln2 output (tf32)
__device__ __align__(16) __nv_bfloat16 g_xnb[MM*DD];         // ln1 output (bf16)
__device__ __align__(16) __nv_bfloat16 g_qbf[HH*MM*AA];      // q  [h][m][a]
__device__ __align__(16) __nv_bfloat16 g_kTp[HH*AA*MM];      // kT pair-packed [h][a/2][2m]
__device__ __align__(16) __nv_bfloat16 g_vT [HH*AA*MM];      // vT plain [h][a][m]
__device__ __align__(16) float g_s  [HH*BB*LL*LL];           // scores fp32
__device__ __align__(16) __nv_bfloat16 g_att[MM*DD];         // attention concat (bf16)
__device__ __align__(16) float g_x1 [MM*DD];
__device__ __align__(16) float g_h  [MM*FF];
// prepped weights
__device__ __align__(16) __nv_bfloat16 g_wqkv[3*HH*DD*AA];   // pair-packed bf16
__device__ __align__(16) __nv_bfloat16 g_wfc [DD*DD];        // pair-packed bf16
__device__ __align__(16) float g_w1 [DD*FF];                 // tf32
__device__ __align__(16) float g_w2 [FF*DD];                 // tf32

// ---------------- helpers ----------------
__device__ __forceinline__ uint32_t f2tf(float f) {
    uint32_t r;
    asm("cvt.rna.tf32.f32 %0, %1;" : "=r"(r) : "f"(f));
    return r;
}
__device__ __forceinline__ float roundtf(float f) {
    return __uint_as_float(f2tf(f));
}
__device__ __forceinline__ uint32_t pack_bf(float lo, float hi) {
    uint16_t l = __bfloat16_as_ushort(__float2bfloat16(lo));
    uint16_t h = __bfloat16_as_ushort(__float2bfloat16(hi));
    return (uint32_t)l | ((uint32_t)h << 16);
}
__device__ __forceinline__ float gelu_exact(float x) {
    return 0.5f * x * (1.0f + erff(x * 0.7071067811865475f));
}
__device__ __forceinline__ uint32_t sptr(const void* p) {
    return (uint32_t)__cvta_generic_to_shared(p);
}
__device__ __forceinline__ void cp16(void* dst, const void* src) {
    asm volatile("cp.async.cg.shared.global [%0], [%1], 16;" :: "r"(sptr(dst)), "l"(src));
}
__device__ __forceinline__ void cp_commit() {
    asm volatile("cp.async.commit_group;");
}
template<int N>
__device__ __forceinline__ void cp_wait() {
    asm volatile("cp.async.wait_group %0;" :: "n"(N));
}

// ---------------- weight prep ----------------
__global__ void round_tf32_kernel(const float4* __restrict__ in,
                                  float4* __restrict__ out, int n4)
{
    int i = blockIdx.x * blockDim.x + threadIdx.x;
    if (i < n4) {
        float4 v = in[i];
        v.x = roundtf(v.x); v.y = roundtf(v.y);
        v.z = roundtf(v.z); v.w = roundtf(v.w);
        out[i] = v;
    }
}

// pack fp32 [K][N] -> bf16 [(k>>1)][2n + (k&1)]   (N power of two, nl = log2 N)
__global__ void pack_bf16_kernel(const float* __restrict__ in,
                                 __nv_bfloat16* __restrict__ out,
                                 int npairs, int nl)
{
    int i = blockIdx.x * blockDim.x + threadIdx.x;
    if (i >= npairs) return;
    int N = 1 << nl;
    int pr = i >> nl;
    int n = i & (N - 1);
    float v0 = in[(size_t)(2 * pr) * N + n];
    float v1 = in[(size_t)(2 * pr + 1) * N + n];
    *(uint32_t*)(out + (size_t)pr * 2 * N + 2 * n) = pack_bf(v0, v1);
}

// ---------------- layernorms ----------------
template<int BF>
__global__ void ln_kernel(const float* __restrict__ x,
                          const float* __restrict__ g,
                          const float* __restrict__ b,
                          float* __restrict__ outf,
                          __nv_bfloat16* __restrict__ outb)
{
    int row = blockIdx.x;
    const float4* xr = (const float4*)(x + (size_t)row * DD);
    __shared__ float red[256];
    float4 vals[4];
    float s = 0.f;
#pragma unroll
    for (int it = 0; it < 4; ++it) {
        float4 v = xr[threadIdx.x + it * 256];
        vals[it] = v;
        s += v.x + v.y + v.z + v.w;
    }
    red[threadIdx.x] = s; __syncthreads();
    for (int st = 128; st > 0; st >>= 1) {
        if (threadIdx.x < st) red[threadIdx.x] += red[threadIdx.x + st];
        __syncthreads();
    }
    float mean = red[0] * (1.f / DD);
    __syncthreads();
    float vs = 0.f;
#pragma unroll
    for (int it = 0; it < 4; ++it) {
        float4 v = vals[it];
        float dx = v.x - mean, dy = v.y - mean, dz = v.z - mean, dw = v.w - mean;
        vs += dx*dx + dy*dy + dz*dz + dw*dw;
    }
    red[threadIdx.x] = vs; __syncthreads();
    for (int st = 128; st > 0; st >>= 1) {
        if (threadIdx.x < st) red[threadIdx.x] += red[threadIdx.x + st];
        __syncthreads();
    }
    float rstd = rsqrtf(red[0] * (1.f / DD) + 1e-5f);
#pragma unroll
    for (int it = 0; it < 4; ++it) {
        int c = (threadIdx.x + it * 256) * 4;
        float4 v = vals[it];
        float4 gg = *(const float4*)(g + c);
        float4 bb = *(const float4*)(b + c);
        float rx = (v.x - mean) * rstd * gg.x + bb.x;
        float ry = (v.y - mean) * rstd * gg.y + bb.y;
        float rz = (v.z - mean) * rstd * gg.z + bb.z;
        float rw = (v.w - mean) * rstd * gg.w + bb.w;
        if (BF) {
            uint32_t* o = (uint32_t*)(outb + (size_t)row * DD);
            o[(threadIdx.x + it * 256) * 2 + 0] = pack_bf(rx, ry);
            o[(threadIdx.x + it * 256) * 2 + 1] = pack_bf(rz, rw);
        } else {
            float4 r;
            r.x = roundtf(rx); r.y = roundtf(ry);
            r.z = roundtf(rz); r.w = roundtf(rw);
            ((float4*)(outf + (size_t)row * DD))[threadIdx.x + it * 256] = r;
        }
    }
}

// =====================================================================
// bf16 GEMM (m16n8k16): C = A[M,K] @ B (B pair-packed [K/2][2N-ish])
// 128x128x64 CTA tile, 128 threads, 4 warps of 64x64, 3-stage cp.async,
// ONE barrier per 64-k tile.
// EPI: 0 raw fp32, 1 plain bf16, 2 packed-transposed bf16 (kT),
//      3 plain-transposed bf16 (vT), 4 bias+residual fp32
// =====================================================================
#define BA_STRIDE 144              // bytes per A row (128 data + 16 pad)
#define BB_STRIDE 528              // bytes per B pair-row (512 data + 16 pad)
#define BA_TILE (128 * BA_STRIDE)
#define BB_TILE (32 * BB_STRIDE)
#define BSTAGE (BA_TILE + BB_TILE)
#define BF_SMEM (3 * BSTAGE)       // 105984

template<int EPI>
__global__ void __launch_bounds__(128, 2)
gemm_bf(const __nv_bfloat16* __restrict__ A, const __nv_bfloat16* __restrict__ Bp,
        float* __restrict__ Cf, __nv_bfloat16* __restrict__ Cb,
        const float* __restrict__ bias, const float* __restrict__ res,
        int M, int N, int K, int ldb2, int zdiv,
        long long sA, long long sB, long long sB2, long long sC)
{
    extern __shared__ char smem[];

    int z = blockIdx.z;
    A  += (long long)z * sA;
    Bp += (long long)(z / zdiv) * sB + (long long)(z % zdiv) * sB2;
    long long co = (long long)z * sC;

    int m0 = blockIdx.y * 128, n0 = blockIdx.x * 128;
    int tid = threadIdx.x;
    int warp = tid >> 5, lane = tid & 31;
    int wm = (warp >> 1) * 64, wn = (warp & 1) * 64;
    int gid = lane >> 2, tig = lane & 3;

    float acc[4][8][4];
#pragma unroll
    for (int a = 0; a < 4; ++a)
#pragma unroll
        for (int b = 0; b < 8; ++b)
#pragma unroll
            for (int c = 0; c < 4; ++c) acc[a][b][c] = 0.f;

    const int T = K >> 6;

    auto load_tile = [&](int t, int st) {
        char* As = smem + st * BSTAGE;
        char* Bs = As + BA_TILE;
#pragma unroll
        for (int i = 0; i < 8; ++i) {          // A: 128 rows x 8 chunks of 16B
            int idx = tid + i * 128;
            int r = idx >> 3, c = idx & 7;
            cp16(As + r * BA_STRIDE + c * 16,
                 A + (size_t)(m0 + r) * K + t * 64 + c * 8);
        }
#pragma unroll
        for (int i = 0; i < 8; ++i) {          // B: 32 pair-rows x 32 chunks
            int idx = tid + i * 128;
            int r = idx >> 5, c = idx & 31;
            cp16(Bs + r * BB_STRIDE + c * 16,
                 Bp + (size_t)(t * 32 + r) * ldb2 + n0 * 2 + c * 8);
        }
    };

    load_tile(0, 0);
    cp_commit();
    if (T > 1) load_tile(1, 1);
    cp_commit();

    int st = 0;
    for (int t = 0; t < T; ++t) {
        cp_wait<1>();
        __syncthreads();
        int st2 = st + 2; if (st2 >= 3) st2 -= 3;
        if (t + 2 < T) load_tile(t + 2, st2);
        cp_commit();

        const char* As = smem + st * BSTAGE;
        const char* Bs = As + BA_TILE;

#pragma unroll
        for (int ksg = 0; ksg < 4; ++ksg) {
            uint32_t af[4][4];
#pragma unroll
            for (int mf = 0; mf < 4; ++mf) {
                const char* base = As + (wm + mf * 16 + gid) * BA_STRIDE + ksg * 32 + tig * 4;
                af[mf][0] = *(const uint32_t*)(base);
                af[mf][1] = *(const uint32_t*)(base + 8 * BA_STRIDE);
                af[mf][2] = *(const uint32_t*)(base + 16);
                af[mf][3] = *(const uint32_t*)(base + 8 * BA_STRIDE + 16);
            }
#pragma unroll
            for (int nf = 0; nf < 8; ++nf) {
                const char* bb = Bs + (ksg * 8 + tig) * BB_STRIDE + (wn + nf * 8 + gid) * 4;
                uint32_t b0 = *(const uint32_t*)(bb);
                uint32_t b1 = *(const uint32_t*)(bb + 4 * BB_STRIDE);
#pragma unroll
                for (int mf = 0; mf < 4; ++mf) {
                    asm volatile(
                        "mma.sync.aligned.m16n8k16.row.col.f32.bf16.bf16.f32 "
                        "{%0,%1,%2,%3}, {%4,%5,%6,%7}, {%8,%9}, {%0,%1,%2,%3};"
                        : "+f"(acc[mf][nf][0]), "+f"(acc[mf][nf][1]),
                          "+f"(acc[mf][nf][2]), "+f"(acc[mf][nf][3])
                        : "r"(af[mf][0]), "r"(af[mf][1]), "r"(af[mf][2]), "r"(af[mf][3]),
                          "r"(b0), "r"(b1));
                }
            }
        }
        if (++st >= 3) st = 0;
    }

    // ---- epilogue ----
    float* CF = Cf + co;
    __nv_bfloat16* CB = Cb + co;
#pragma unroll
    for (int mf = 0; mf < 4; ++mf) {
        int r0 = m0 + wm + mf * 16 + gid;
#pragma unroll
        for (int nf = 0; nf < 8; ++nf) {
            int c = n0 + wn + nf * 8 + tig * 2;
#pragma unroll
            for (int half = 0; half < 2; ++half) {
                int r = r0 + half * 8;
                float v0 = acc[mf][nf][half * 2 + 0];
                float v1 = acc[mf][nf][half * 2 + 1];
                if (EPI == 0) {
                    *(float2*)(CF + (size_t)r * N + c) = make_float2(v0, v1);
                } else if (EPI == 1) {
                    *(uint32_t*)(CB + (size_t)r * N + c) = pack_bf(v0, v1);
                } else if (EPI == 2) {
                    *(uint32_t*)(CB + (size_t)(c >> 1) * (2 * (size_t)M) + 2 * r) = pack_bf(v0, v1);
                } else if (EPI == 3) {
                    CB[(size_t)c * M + r]       = __float2bfloat16(v0);
                    CB[(size_t)(c + 1) * M + r] = __float2bfloat16(v1);
                } else {
                    v0 += bias[c]; v1 += bias[c + 1];
                    size_t off = (size_t)r * N + c;
                    v0 += res[off]; v1 += res[off + 1];
                    *(float2*)(CF + off) = make_float2(v0, v1);
                }
            }
        }
    }
}

// =====================================================================
// tf32 GEMM (MLP): 3-stage, 128 thr, 4 warps 64x64, 1 barrier/k-tile
// EPI: 1 bias+res, 2 bias+gelu+round
// =====================================================================
#define LDAS 36
#define LDBS 136
#define A_TILE (128 * LDAS)
#define B_TILE (32 * LDBS)
#define NN_SMEM (3 * (A_TILE + B_TILE) * 4)

template<int EPI>
__global__ void __launch_bounds__(128, 2)
gemm_nn_pipe(const float* __restrict__ A, const float* __restrict__ B,
             float* __restrict__ C, const float* __restrict__ bias,
             const float* __restrict__ res,
             int M, int N, int K)
{
    extern __shared__ float smemf[];

    int m0 = blockIdx.y * 128, n0 = blockIdx.x * 128;
    int tid = threadIdx.x;
    int warp = tid >> 5, lane = tid & 31;
    int wm = (warp >> 1) * 64, wn = (warp & 1) * 64;
    int gid = lane >> 2, tig = lane & 3;

    int a_rm = tid >> 3, a_c4 = (tid & 7) * 4;
    int b_rk = tid >> 5, b_c4 = (tid & 31) * 4;

    float acc[4][8][4];
#pragma unroll
    for (int a = 0; a < 4; ++a)
#pragma unroll
        for (int b = 0; b < 8; ++b)
#pragma unroll
            for (int c = 0; c < 4; ++c) acc[a][b][c] = 0.f;

    const int kTiles = K >> 5;

    auto load_tile = [&](int t, int st) {
        float* As = smemf + st * (A_TILE + B_TILE);
        float* Bs = As + A_TILE;
        const float* Ag = A + (size_t)(m0 + a_rm) * K + t * 32 + a_c4;
        const float* Bg = B + (size_t)(t * 32 + b_rk) * N + n0 + b_c4;
        float* Ad = As + a_rm * LDAS + a_c4;
        float* Bd = Bs + b_rk * LDBS + b_c4;
#pragma unroll
        for (int it = 0; it < 8; ++it) {
            cp16(Ad + it * 16 * LDAS, Ag + (size_t)it * 16 * K);
            cp16(Bd + it * 4 * LDBS, Bg + (size_t)it * 4 * N);
        }
    };

    load_tile(0, 0);
    cp_commit();
    if (kTiles > 1) load_tile(1, 1);
    cp_commit();

    int st = 0;
    for (int t = 0; t < kTiles; ++t) {
        cp_wait<1>();
        __syncthreads();
        int st2 = st + 2; if (st2 >= 3) st2 -= 3;
        if (t + 2 < kTiles) load_tile(t + 2, st2);
        cp_commit();

        const float* As_s = smemf + st * (A_TILE + B_TILE);
        const float* Bs_s = As_s + A_TILE;

#pragma unroll
        for (int ks = 0; ks < 4; ++ks) {
            uint32_t af[4][4];
#pragma unroll
            for (int mf = 0; mf < 4; ++mf) {
                const float* p = &As_s[(wm + mf * 16 + gid) * LDAS + ks * 8 + tig];
                af[mf][0] = __float_as_uint(p[0]);
                af[mf][1] = __float_as_uint(p[8 * LDAS]);
                af[mf][2] = __float_as_uint(p[4]);
                af[mf][3] = __float_as_uint(p[8 * LDAS + 4]);
            }
#pragma unroll
            for (int nf = 0; nf < 8; ++nf) {
                const float* p = &Bs_s[(ks * 8 + tig) * LDBS + wn + nf * 8 + gid];
                uint32_t b0 = __float_as_uint(p[0]);
                uint32_t b1 = __float_as_uint(p[4 * LDBS]);
#pragma unroll
                for (int mf = 0; mf < 4; ++mf) {
                    asm volatile(
                        "mma.sync.aligned.m16n8k8.row.col.f32.tf32.tf32.f32 "
                        "{%0,%1,%2,%3}, {%4,%5,%6,%7}, {%8,%9}, {%0,%1,%2,%3};"
                        : "+f"(acc[mf][nf][0]), "+f"(acc[mf][nf][1]),
                          "+f"(acc[mf][nf][2]), "+f"(acc[mf][nf][3])
                        : "r"(af[mf][0]), "r"(af[mf][1]), "r"(af[mf][2]), "r"(af[mf][3]),
                          "r"(b0), "r"(b1));
                }
            }
        }
        if (++st >= 3) st = 0;
    }

#pragma unroll
    for (int mf = 0; mf < 4; ++mf) {
        int r0 = m0 + wm + mf * 16 + gid;
#pragma unroll
        for (int nf = 0; nf < 8; ++nf) {
            int c = n0 + wn + nf * 8 + tig * 2;
#pragma unroll
            for (int half = 0; half < 2; ++half) {
                int r = r0 + half * 8;
                float v0 = acc[mf][nf][half * 2 + 0] + bias[c];
                float v1 = acc[mf][nf][half * 2 + 1] + bias[c + 1];
                if (EPI == 2) {
                    v0 = roundtf(gelu_exact(v0));
                    v1 = roundtf(gelu_exact(v1));
                }
                size_t off = (size_t)r * N + c;
                if (EPI == 1) { v0 += res[off]; v1 += res[off + 1]; }
                *(float2*)(C + off) = make_float2(v0, v1);
            }
        }
    }
}

// ---------------- column softmax + p * v^T + head concat -> att (bf16) ----------------
__global__ void softmax_att_kernel(const float* __restrict__ s,
                                   const __nv_bfloat16* __restrict__ vT,
                                   __nv_bfloat16* __restrict__ att)
{
    int z = blockIdx.y;          // z = h*B + b
    int h = z >> 3, b = z & 7;
    int j0 = blockIdx.x * 32;
    int tx = threadIdx.x, ty = threadIdx.y;   // 32 x 16
    const float* sp = s + (size_t)z * LL * LL;
    const float rs = 0.04419417382415922f;    // 1/sqrt(512)
    int j = j0 + tx;

    float part = 0.f;
    for (int it = 0; it < 32; ++it) {
        int i = it * 16 + ty;
        float val = (j <= i) ? sp[(size_t)i * LL + j] : -1000.f;
        part += expf(val * rs);
    }
    __shared__ float red[16][32];
    __shared__ float cinv[32];
    red[ty][tx] = part; __syncthreads();
    if (ty < 8) red[ty][tx] += red[ty + 8][tx];
    __syncthreads();
    if (ty < 4) red[ty][tx] += red[ty + 4][tx];
    __syncthreads();
    if (ty < 2) red[ty][tx] += red[ty + 2][tx];
    __syncthreads();
    if (ty == 0) cinv[tx] = 1.f / (red[0][tx] + red[1][tx]);
    __syncthreads();
    float ci = cinv[tx];

    const __nv_bfloat16* vrow = vT + (size_t)h * AA * MM + (size_t)b * LL + j;
    size_t attb = (size_t)b * LL * DD + (size_t)h * AA + j;
    for (int it = 0; it < 32; ++it) {
        int i = it * 16 + ty;
        float val = (j <= i) ? sp[(size_t)i * LL + j] : -1000.f;
        float p = expf(val * rs) * ci;
        float vv = __bfloat162float(vrow[(size_t)i * MM]);
        att[attb + (size_t)i * DD] = __float2bfloat16(p * vv);
    }
}

// ---------------- launch ----------------
extern "C" void kernel_launch(void* const* d_in, const int* in_sizes, int n_in,
                              void* d_out, int out_size)
{
    (void)in_sizes; (void)n_in; (void)out_size;
    const float* x    = (const float*)d_in[0];
    const float* Wq   = (const float*)d_in[2];
    const float* Wk   = (const float*)d_in[3];
    const float* Wv   = (const float*)d_in[4];
    const float* fc_w = (const float*)d_in[5];
    const float* fc_b = (const float*)d_in[6];
    const float* ln1g = (const float*)d_in[7];
    const float* ln1b = (const float*)d_in[8];
    const float* W1   = (const float*)d_in[9];
    const float* b1   = (const float*)d_in[10];
    const float* W2   = (const float*)d_in[11];
    const float* b2   = (const float*)d_in[12];
    const float* ln2g = (const float*)d_in[13];
    const float* ln2b = (const float*)d_in[14];
    float* out = (float*)d_out;

    float *xn, *s, *x1, *hb, *w1, *w2;
    __nv_bfloat16 *xnb, *qbf, *kTp, *vT, *att, *wqkv, *wfc;
    cudaGetSymbolAddress((void**)&xn,   g_xn);
    cudaGetSymbolAddress((void**)&xnb,  g_xnb);
    cudaGetSymbolAddress((void**)&qbf,  g_qbf);
    cudaGetSymbolAddress((void**)&kTp,  g_kTp);
    cudaGetSymbolAddress((void**)&vT,   g_vT);
    cudaGetSymbolAddress((void**)&s,    g_s);
    cudaGetSymbolAddress((void**)&att,  g_att);
    cudaGetSymbolAddress((void**)&x1,   g_x1);
    cudaGetSymbolAddress((void**)&hb,   g_h);
    cudaGetSymbolAddress((void**)&wqkv, g_wqkv);
    cudaGetSymbolAddress((void**)&wfc,  g_wfc);
    cudaGetSymbolAddress((void**)&w1,   g_w1);
    cudaGetSymbolAddress((void**)&w2,   g_w2);

    cudaFuncSetAttribute(gemm_bf<0>, cudaFuncAttributeMaxDynamicSharedMemorySize, BF_SMEM);
    cudaFuncSetAttribute(gemm_bf<1>, cudaFuncAttributeMaxDynamicSharedMemorySize, BF_SMEM);
    cudaFuncSetAttribute(gemm_bf<2>, cudaFuncAttributeMaxDynamicSharedMemorySize, BF_SMEM);
    cudaFuncSetAttribute(gemm_bf<3>, cudaFuncAttributeMaxDynamicSharedMemorySize, BF_SMEM);
    cudaFuncSetAttribute(gemm_bf<4>, cudaFuncAttributeMaxDynamicSharedMemorySize, BF_SMEM);
    cudaFuncSetAttribute(gemm_nn_pipe<1>, cudaFuncAttributeMaxDynamicSharedMemorySize, NN_SMEM);
    cudaFuncSetAttribute(gemm_nn_pipe<2>, cudaFuncAttributeMaxDynamicSharedMemorySize, NN_SMEM);

    const long long HDA = (long long)HH * DD * AA;
    const long long HAM = (long long)AA * MM;      // per-head kT/vT block

    // ---- prep ----
    ln_kernel<1><<<MM, 256>>>(x, ln1g, ln1b, nullptr, xnb);
    {
        int npq = HH * DD * AA / 2;   // 8.4M pairs, N=512 -> nl=9
        pack_bf16_kernel<<<(npq + 255) / 256, 256>>>(Wq, wqkv + 0 * HDA, npq, 9);
        pack_bf16_kernel<<<(npq + 255) / 256, 256>>>(Wk, wqkv + 1 * HDA, npq, 9);
        pack_bf16_kernel<<<(npq + 255) / 256, 256>>>(Wv, wqkv + 2 * HDA, npq, 9);
        int npf = DD * DD / 2;        // nl=12
        pack_bf16_kernel<<<(npf + 255) / 256, 256>>>(fc_w, wfc, npf, 12);
        int n4 = DD * FF / 4;
        round_tf32_kernel<<<n4 / 256, 256>>>((const float4*)W1, (float4*)w1, n4);
        round_tf32_kernel<<<n4 / 256, 256>>>((const float4*)W2, (float4*)w2, n4);
    }

    // ---- QKV (bf16), z = head ----
    {
        dim3 grid(AA / 128, MM / 128, HH);
        // q: plain bf16 [h][m][a]
        gemm_bf<1><<<grid, 128, BF_SMEM>>>(xnb, wqkv + 0 * HDA, nullptr, qbf,
                                           nullptr, nullptr,
                                           MM, AA, DD, 2 * AA, 1,
                                           0, (long long)DD * AA, 0, (long long)MM * AA);
        // k: pair-packed transposed [h][a/2][2m]
        gemm_bf<2><<<grid, 128, BF_SMEM>>>(xnb, wqkv + 1 * HDA, nullptr, kTp,
                                           nullptr, nullptr,
                                           MM, AA, DD, 2 * AA, 1,
                                           0, (long long)DD * AA, 0, HAM);
        // v: plain transposed [h][a][m]
        gemm_bf<3><<<grid, 128, BF_SMEM>>>(xnb, wqkv + 2 * HDA, nullptr, vT,
                                           nullptr, nullptr,
                                           MM, AA, DD, 2 * AA, 1,
                                           0, (long long)DD * AA, 0, HAM);
    }

    // ---- S = q @ k^T (bf16, 64 batches z = h*8 + b) ----
    {
        dim3 grid(LL / 128, LL / 128, HH * BB);
        gemm_bf<0><<<grid, 128, BF_SMEM>>>(qbf, kTp, s, nullptr,
                                           nullptr, nullptr,
                                           LL, LL, AA, 2 * MM, 8,
                                           (long long)LL * AA, HAM, 2LL * LL,
                                           (long long)LL * LL);
    }

    // ---- column softmax + p*v^T + concat (bf16 att) ----
    {
        dim3 grid(LL / 32, HH * BB);
        dim3 blk(32, 16);
        softmax_att_kernel<<<grid, blk>>>(s, vT, att);
    }

    // ---- x1 = x + att @ fc_w + fc_b (bf16 gemm, fp32 out) ----
    {
        dim3 grid(DD / 128, MM / 128, 1);
        gemm_bf<4><<<grid, 128, BF_SMEM>>>(att, wfc, x1, nullptr,
                                           fc_b, x,
                                           MM, DD, DD, 2 * DD, 1,
                                           0, 0, 0, 0);
    }

    // ---- MLP (tf32) ----
    ln_kernel<0><<<MM, 256>>>(x1, ln2g, ln2b, xn, nullptr);
    {
        dim3 grid(FF / 128, MM / 128, 1);
        gemm_nn_pipe<2><<<grid, 128, NN_SMEM>>>(xn, w1, hb, b1, nullptr, MM, FF, DD);
    }
    {
        dim3 grid(DD / 128, MM / 128, 1);
        gemm_nn_pipe<1><<<grid, 128, NN_SMEM>>>(hb, w2, out, b2, x1, MM, DD, FF);
    }
}

// round 8
// speedup vs baseline: 2.6264x; 1.5354x over previous
#include <cuda_runtime.h>
#include <cuda_fp16.h>
#include <cstdint>
#include <math.h>

#define BB 8
#define LL 512
#define DD 4096
#define HH 8
#define FF 16384
#define AA 512       // per-head dim == L
#define MM (BB*LL)   // 4096

// ---------------- scratch (device globals: allocation-free) ----------------
__device__ __align__(16) __half g_xnb[MM*DD];        // ln1 out fp16
__device__ __align__(16) __half g_xn2[MM*DD];        // ln2 out fp16
__device__ __align__(16) __half g_q  [HH*MM*AA];     // q  [h][m][a]
__device__ __align__(16) __half g_kTp[HH*AA*MM];     // kT pair-packed [h][a/2][2m]
__device__ __align__(16) __half g_vT [HH*AA*MM];     // vT plain [h][a][m]
__device__ __align__(16) float  g_s  [HH*BB*LL*LL];  // scores fp32
__device__ __align__(16) __half g_att[MM*DD];        // attention concat fp16
__device__ __align__(16) float  g_x1 [MM*DD];        // residual fp32
__device__ __align__(16) __half g_h  [MM*FF];        // MLP hidden fp16
// prepped weights (fp16, pair-packed along K)
__device__ __align__(16) __half g_wqkv[3*HH*DD*AA];
__device__ __align__(16) __half g_wfc [DD*DD];
__device__ __align__(16) __half g_w1  [DD*FF];
__device__ __align__(16) __half g_w2  [FF*DD];

// ---------------- helpers ----------------
__device__ __forceinline__ uint32_t pack_hf(float lo, float hi) {
    __half2 h = __floats2half2_rn(lo, hi);
    return *(uint32_t*)&h;
}
__device__ __forceinline__ float gelu_exact(float x) {
    return 0.5f * x * (1.0f + erff(x * 0.7071067811865475f));
}
__device__ __forceinline__ uint32_t sptr(const void* p) {
    return (uint32_t)__cvta_generic_to_shared(p);
}
__device__ __forceinline__ void cp16(void* dst, const void* src) {
    asm volatile("cp.async.cg.shared.global [%0], [%1], 16;" :: "r"(sptr(dst)), "l"(src));
}
__device__ __forceinline__ void cp_commit() {
    asm volatile("cp.async.commit_group;");
}
template<int N>
__device__ __forceinline__ void cp_wait() {
    asm volatile("cp.async.wait_group %0;" :: "n"(N));
}

// ---------------- fused weight prep: fp16 pair-pack ALL weights, 1 launch ----
// pack fp32 [K][N] -> fp16 [(k>>1)][2n + (k&1)]  (N = 1<<nl)
__device__ __forceinline__ void pack_one(const float* __restrict__ in,
                                         __half* __restrict__ out,
                                         long long pairidx, int nl)
{
    long long N = 1LL << nl;
    long long pr = pairidx >> nl;
    long long n = pairidx & (N - 1);
    float v0 = in[(2 * pr) * N + n];
    float v1 = in[(2 * pr + 1) * N + n];
    *(uint32_t*)(out + pr * 2 * N + 2 * n) = pack_hf(v0, v1);
}

#define QP  ((long long)HH*DD*AA/2)   // 8,388,608 pairs per QKV matrix
#define FCP ((long long)DD*DD/2)      // 8,388,608
#define W1P ((long long)DD/2*FF)      // 33,554,432
#define W2P ((long long)FF/2*DD)      // 33,554,432
#define PREP_PAIRS (3*QP + FCP + W1P + W2P)   // 100,663,296

__global__ void prep_weights(const float* __restrict__ Wq, const float* __restrict__ Wk,
                             const float* __restrict__ Wv, const float* __restrict__ Wfc,
                             const float* __restrict__ W1, const float* __restrict__ W2,
                             __half* __restrict__ wqkv, __half* __restrict__ wfc,
                             __half* __restrict__ w1, __half* __restrict__ w2)
{
    long long i = (long long)blockIdx.x * blockDim.x + threadIdx.x;
    if (i < 3 * QP) {
        int w = (int)(i / QP);
        long long r = i - (long long)w * QP;
        const float* src = (w == 0) ? Wq : (w == 1) ? Wk : Wv;
        pack_one(src, wqkv + (long long)w * (2 * QP), r, 9);
    } else if (i < 3 * QP + FCP) {
        pack_one(Wfc, wfc, i - 3 * QP, 12);
    } else if (i < 3 * QP + FCP + W1P) {
        pack_one(W1, w1, i - (3 * QP + FCP), 14);
    } else {
        pack_one(W2, w2, i - (3 * QP + FCP + W1P), 12);
    }
}

// ---------------- layernorm (fp16 output) ----------------
__global__ void ln_kernel(const float* __restrict__ x,
                          const float* __restrict__ g,
                          const float* __restrict__ b,
                          __half* __restrict__ outb)
{
    int row = blockIdx.x;
    const float4* xr = (const float4*)(x + (size_t)row * DD);
    __shared__ float red[256];
    float4 vals[4];
    float s = 0.f;
#pragma unroll
    for (int it = 0; it < 4; ++it) {
        float4 v = xr[threadIdx.x + it * 256];
        vals[it] = v;
        s += v.x + v.y + v.z + v.w;
    }
    red[threadIdx.x] = s; __syncthreads();
    for (int st = 128; st > 0; st >>= 1) {
        if (threadIdx.x < st) red[threadIdx.x] += red[threadIdx.x + st];
        __syncthreads();
    }
    float mean = red[0] * (1.f / DD);
    __syncthreads();
    float vs = 0.f;
#pragma unroll
    for (int it = 0; it < 4; ++it) {
        float4 v = vals[it];
        float dx = v.x - mean, dy = v.y - mean, dz = v.z - mean, dw = v.w - mean;
        vs += dx*dx + dy*dy + dz*dz + dw*dw;
    }
    red[threadIdx.x] = vs; __syncthreads();
    for (int st = 128; st > 0; st >>= 1) {
        if (threadIdx.x < st) red[threadIdx.x] += red[threadIdx.x + st];
        __syncthreads();
    }
    float rstd = rsqrtf(red[0] * (1.f / DD) + 1e-5f);
#pragma unroll
    for (int it = 0; it < 4; ++it) {
        int c = (threadIdx.x + it * 256) * 4;
        float4 v = vals[it];
        float4 gg = *(const float4*)(g + c);
        float4 bb = *(const float4*)(b + c);
        float rx = (v.x - mean) * rstd * gg.x + bb.x;
        float ry = (v.y - mean) * rstd * gg.y + bb.y;
        float rz = (v.z - mean) * rstd * gg.z + bb.z;
        float rw = (v.w - mean) * rstd * gg.w + bb.w;
        uint32_t* o = (uint32_t*)(outb + (size_t)row * DD);
        o[(threadIdx.x + it * 256) * 2 + 0] = pack_hf(rx, ry);
        o[(threadIdx.x + it * 256) * 2 + 1] = pack_hf(rz, rw);
    }
}

// =====================================================================
// fp16 GEMM (m16n8k16, fp32 accum): C = A[M,K] @ B (B pair-packed)
// 128x128x64 CTA tile, 128 threads, 4 warps of 64x64, 3-stage cp.async,
// ONE barrier per 64-k tile.
// EPI: 0 raw fp32, 1 plain fp16, 2 packed-transposed fp16 (kT),
//      3 plain-transposed fp16 (vT), 4 bias+residual fp32,
//      5 bias+gelu fp16
// =====================================================================
#define BA_STRIDE 144              // bytes per A row (128 data + 16 pad)
#define BB_STRIDE 528              // bytes per B pair-row (512 data + 16 pad)
#define BA_TILE (128 * BA_STRIDE)
#define BB_TILE (32 * BB_STRIDE)
#define BSTAGE (BA_TILE + BB_TILE)
#define HF_SMEM (3 * BSTAGE)       // 105984

template<int EPI>
__global__ void __launch_bounds__(128, 2)
gemm_hf(const __half* __restrict__ A, const __half* __restrict__ Bp,
        float* __restrict__ Cf, __half* __restrict__ Cb,
        const float* __restrict__ bias, const float* __restrict__ res,
        int M, int N, int K, int ldb2, int zdiv,
        long long sA, long long sB, long long sB2, long long sC)
{
    extern __shared__ char smem[];

    int z = blockIdx.z;
    A  += (long long)z * sA;
    Bp += (long long)(z / zdiv) * sB + (long long)(z % zdiv) * sB2;
    long long co = (long long)z * sC;

    int m0 = blockIdx.y * 128, n0 = blockIdx.x * 128;
    int tid = threadIdx.x;
    int warp = tid >> 5, lane = tid & 31;
    int wm = (warp >> 1) * 64, wn = (warp & 1) * 64;
    int gid = lane >> 2, tig = lane & 3;

    float acc[4][8][4];
#pragma unroll
    for (int a = 0; a < 4; ++a)
#pragma unroll
        for (int b = 0; b < 8; ++b)
#pragma unroll
            for (int c = 0; c < 4; ++c) acc[a][b][c] = 0.f;

    const int T = K >> 6;

    auto load_tile = [&](int t, int st) {
        char* As = smem + st * BSTAGE;
        char* Bs = As + BA_TILE;
#pragma unroll
        for (int i = 0; i < 8; ++i) {          // A: 128 rows x 8 chunks of 16B
            int idx = tid + i * 128;
            int r = idx >> 3, c = idx & 7;
            cp16(As + r * BA_STRIDE + c * 16,
                 A + (size_t)(m0 + r) * K + t * 64 + c * 8);
        }
#pragma unroll
        for (int i = 0; i < 8; ++i) {          // B: 32 pair-rows x 32 chunks
            int idx = tid + i * 128;
            int r = idx >> 5, c = idx & 31;
            cp16(Bs + r * BB_STRIDE + c * 16,
                 Bp + (size_t)(t * 32 + r) * ldb2 + n0 * 2 + c * 8);
        }
    };

    load_tile(0, 0);
    cp_commit();
    if (T > 1) load_tile(1, 1);
    cp_commit();

    int st = 0;
    for (int t = 0; t < T; ++t) {
        cp_wait<1>();
        __syncthreads();
        int st2 = st + 2; if (st2 >= 3) st2 -= 3;
        if (t + 2 < T) load_tile(t + 2, st2);
        cp_commit();

        const char* As = smem + st * BSTAGE;
        const char* Bs = As + BA_TILE;

#pragma unroll
        for (int ksg = 0; ksg < 4; ++ksg) {
            uint32_t af[4][4];
#pragma unroll
            for (int mf = 0; mf < 4; ++mf) {
                const char* base = As + (wm + mf * 16 + gid) * BA_STRIDE + ksg * 32 + tig * 4;
                af[mf][0] = *(const uint32_t*)(base);
                af[mf][1] = *(const uint32_t*)(base + 8 * BA_STRIDE);
                af[mf][2] = *(const uint32_t*)(base + 16);
                af[mf][3] = *(const uint32_t*)(base + 8 * BA_STRIDE + 16);
            }
#pragma unroll
            for (int nf = 0; nf < 8; ++nf) {
                const char* bb = Bs + (ksg * 8 + tig) * BB_STRIDE + (wn + nf * 8 + gid) * 4;
                uint32_t b0 = *(const uint32_t*)(bb);
                uint32_t b1 = *(const uint32_t*)(bb + 4 * BB_STRIDE);
#pragma unroll
                for (int mf = 0; mf < 4; ++mf) {
                    asm volatile(
                        "mma.sync.aligned.m16n8k16.row.col.f32.f16.f16.f32 "
                        "{%0,%1,%2,%3}, {%4,%5,%6,%7}, {%8,%9}, {%0,%1,%2,%3};"
                        : "+f"(acc[mf][nf][0]), "+f"(acc[mf][nf][1]),
                          "+f"(acc[mf][nf][2]), "+f"(acc[mf][nf][3])
                        : "r"(af[mf][0]), "r"(af[mf][1]), "r"(af[mf][2]), "r"(af[mf][3]),
                          "r"(b0), "r"(b1));
                }
            }
        }
        if (++st >= 3) st = 0;
    }

    // ---- epilogue ----
    float* CF = Cf + co;
    __half* CB = Cb + co;
#pragma unroll
    for (int mf = 0; mf < 4; ++mf) {
        int r0 = m0 + wm + mf * 16 + gid;
#pragma unroll
        for (int nf = 0; nf < 8; ++nf) {
            int c = n0 + wn + nf * 8 + tig * 2;
#pragma unroll
            for (int half = 0; half < 2; ++half) {
                int r = r0 + half * 8;
                float v0 = acc[mf][nf][half * 2 + 0];
                float v1 = acc[mf][nf][half * 2 + 1];
                if (EPI == 0) {
                    *(float2*)(CF + (size_t)r * N + c) = make_float2(v0, v1);
                } else if (EPI == 1) {
                    *(uint32_t*)(CB + (size_t)r * N + c) = pack_hf(v0, v1);
                } else if (EPI == 2) {
                    *(uint32_t*)(CB + (size_t)(c >> 1) * (2 * (size_t)M) + 2 * r) = pack_hf(v0, v1);
                } else if (EPI == 3) {
                    CB[(size_t)c * M + r]       = __float2half(v0);
                    CB[(size_t)(c + 1) * M + r] = __float2half(v1);
                } else if (EPI == 4) {
                    v0 += bias[c]; v1 += bias[c + 1];
                    size_t off = (size_t)r * N + c;
                    v0 += res[off]; v1 += res[off + 1];
                    *(float2*)(CF + off) = make_float2(v0, v1);
                } else {   // 5: bias + gelu -> fp16
                    v0 = gelu_exact(v0 + bias[c]);
                    v1 = gelu_exact(v1 + bias[c + 1]);
                    *(uint32_t*)(CB + (size_t)r * N + c) = pack_hf(v0, v1);
                }
            }
        }
    }
}

// ---------------- column softmax + p * v^T + head concat -> att (fp16) ----------------
__global__ void softmax_att_kernel(const float* __restrict__ s,
                                   const __half* __restrict__ vT,
                                   __half* __restrict__ att)
{
    int z = blockIdx.y;          // z = h*B + b
    int h = z >> 3, b = z & 7;
    int j0 = blockIdx.x * 32;
    int tx = threadIdx.x, ty = threadIdx.y;   // 32 x 16
    const float* sp = s + (size_t)z * LL * LL;
    const float rs = 0.04419417382415922f;    // 1/sqrt(512)
    int j = j0 + tx;

    float part = 0.f;
    for (int it = 0; it < 32; ++it) {
        int i = it * 16 + ty;
        float val = (j <= i) ? sp[(size_t)i * LL + j] : -1000.f;
        part += expf(val * rs);
    }
    __shared__ float red[16][32];
    __shared__ float cinv[32];
    red[ty][tx] = part; __syncthreads();
    if (ty < 8) red[ty][tx] += red[ty + 8][tx];
    __syncthreads();
    if (ty < 4) red[ty][tx] += red[ty + 4][tx];
    __syncthreads();
    if (ty < 2) red[ty][tx] += red[ty + 2][tx];
    __syncthreads();
    if (ty == 0) cinv[tx] = 1.f / (red[0][tx] + red[1][tx]);
    __syncthreads();
    float ci = cinv[tx];

    const __half* vrow = vT + (size_t)h * AA * MM + (size_t)b * LL + j;
    size_t attb = (size_t)b * LL * DD + (size_t)h * AA + j;
    for (int it = 0; it < 32; ++it) {
        int i = it * 16 + ty;
        float val = (j <= i) ? sp[(size_t)i * LL + j] : -1000.f;
        float p = expf(val * rs) * ci;
        float vv = __half2float(vrow[(size_t)i * MM]);
        att[attb + (size_t)i * DD] = __float2half(p * vv);
    }
}

// ---------------- launch ----------------
extern "C" void kernel_launch(void* const* d_in, const int* in_sizes, int n_in,
                              void* d_out, int out_size)
{
    (void)in_sizes; (void)n_in; (void)out_size;
    const float* x    = (const float*)d_in[0];
    const float* Wq   = (const float*)d_in[2];
    const float* Wk   = (const float*)d_in[3];
    const float* Wv   = (const float*)d_in[4];
    const float* fc_w = (const float*)d_in[5];
    const float* fc_b = (const float*)d_in[6];
    const float* ln1g = (const float*)d_in[7];
    const float* ln1b = (const float*)d_in[8];
    const float* W1   = (const float*)d_in[9];
    const float* b1   = (const float*)d_in[10];
    const float* W2   = (const float*)d_in[11];
    const float* b2   = (const float*)d_in[12];
    const float* ln2g = (const float*)d_in[13];
    const float* ln2b = (const float*)d_in[14];
    float* out = (float*)d_out;

    float *s, *x1;
    __half *xnb, *xn2, *q, *kTp, *vT, *att, *hb, *wqkv, *wfc, *w1, *w2;
    cudaGetSymbolAddress((void**)&xnb,  g_xnb);
    cudaGetSymbolAddress((void**)&xn2,  g_xn2);
    cudaGetSymbolAddress((void**)&q,    g_q);
    cudaGetSymbolAddress((void**)&kTp,  g_kTp);
    cudaGetSymbolAddress((void**)&vT,   g_vT);
    cudaGetSymbolAddress((void**)&s,    g_s);
    cudaGetSymbolAddress((void**)&att,  g_att);
    cudaGetSymbolAddress((void**)&x1,   g_x1);
    cudaGetSymbolAddress((void**)&hb,   g_h);
    cudaGetSymbolAddress((void**)&wqkv, g_wqkv);
    cudaGetSymbolAddress((void**)&wfc,  g_wfc);
    cudaGetSymbolAddress((void**)&w1,   g_w1);
    cudaGetSymbolAddress((void**)&w2,   g_w2);

    cudaFuncSetAttribute(gemm_hf<0>, cudaFuncAttributeMaxDynamicSharedMemorySize, HF_SMEM);
    cudaFuncSetAttribute(gemm_hf<1>, cudaFuncAttributeMaxDynamicSharedMemorySize, HF_SMEM);
    cudaFuncSetAttribute(gemm_hf<2>, cudaFuncAttributeMaxDynamicSharedMemorySize, HF_SMEM);
    cudaFuncSetAttribute(gemm_hf<3>, cudaFuncAttributeMaxDynamicSharedMemorySize, HF_SMEM);
    cudaFuncSetAttribute(gemm_hf<4>, cudaFuncAttributeMaxDynamicSharedMemorySize, HF_SMEM);
    cudaFuncSetAttribute(gemm_hf<5>, cudaFuncAttributeMaxDynamicSharedMemorySize, HF_SMEM);

    const long long HDA = (long long)HH * DD * AA;
    const long long HAM = (long long)AA * MM;      // per-head kT/vT block

    // launch 0: ln1
    ln_kernel<<<MM, 256>>>(x, ln1g, ln1b, xnb);

    // launch 1: fused weight prep (fp16 pair-pack, all weights)
    prep_weights<<<(unsigned)(PREP_PAIRS / 256), 256>>>(
        Wq, Wk, Wv, fc_w, W1, W2, wqkv, wfc, w1, w2);

    // launches 2-4: QKV (z = head)
    {
        dim3 grid(AA / 128, MM / 128, HH);
        gemm_hf<1><<<grid, 128, HF_SMEM>>>(xnb, wqkv + 0 * HDA, nullptr, q,
                                           nullptr, nullptr,
                                           MM, AA, DD, 2 * AA, 1,
                                           0, (long long)DD * AA, 0, (long long)MM * AA);
        gemm_hf<2><<<grid, 128, HF_SMEM>>>(xnb, wqkv + 1 * HDA, nullptr, kTp,
                                           nullptr, nullptr,
                                           MM, AA, DD, 2 * AA, 1,
                                           0, (long long)DD * AA, 0, HAM);
        gemm_hf<3><<<grid, 128, HF_SMEM>>>(xnb, wqkv + 2 * HDA, nullptr, vT,
                                           nullptr, nullptr,
                                           MM, AA, DD, 2 * AA, 1,
                                           0, (long long)DD * AA, 0, HAM);
    }

    // launch 5 (ncu target): S = q @ k^T (64 batches, z = h*8 + b)
    {
        dim3 grid(LL / 128, LL / 128, HH * BB);
        gemm_hf<0><<<grid, 128, HF_SMEM>>>(q, kTp, s, nullptr,
                                           nullptr, nullptr,
                                           LL, LL, AA, 2 * MM, 8,
                                           (long long)LL * AA, HAM, 2LL * LL,
                                           (long long)LL * LL);
    }

    // launch 6: column softmax + p*v^T + concat
    {
        dim3 grid(LL / 32, HH * BB);
        dim3 blk(32, 16);
        softmax_att_kernel<<<grid, blk>>>(s, vT, att);
    }

    // launch 7: x1 = x + att @ fc_w + fc_b
    {
        dim3 grid(DD / 128, MM / 128, 1);
        gemm_hf<4><<<grid, 128, HF_SMEM>>>(att, wfc, x1, nullptr,
                                           fc_b, x,
                                           MM, DD, DD, 2 * DD, 1,
                                           0, 0, 0, 0);
    }

    // launch 8: ln2
    ln_kernel<<<MM, 256>>>(x1, ln2g, ln2b, xn2);

    // launch 9: h = gelu(xn2 @ W1 + b1) -> fp16
    {
        dim3 grid(FF / 128, MM / 128, 1);
        gemm_hf<5><<<grid, 128, HF_SMEM>>>(xn2, w1, nullptr, hb,
                                           b1, nullptr,
                                           MM, FF, DD, 2 * FF, 1,
                                           0, 0, 0, 0);
    }

    // launch 10: out = x1 + h @ W2 + b2
    {
        dim3 grid(DD / 128, MM / 128, 1);
        gemm_hf<4><<<grid, 128, HF_SMEM>>>(hb, w2, out, nullptr,
                                           b2, x1,
                                           MM, DD, FF, 2 * DD, 1,
                                           0, 0, 0, 0);
    }
}

// round 9
// speedup vs baseline: 2.7712x; 1.0551x over previous
#include <cuda_runtime.h>
#include <cuda_fp16.h>
#include <cstdint>
#include <math.h>

#define BB 8
#define LL 512
#define DD 4096
#define HH 8
#define FF 16384
#define AA 512       // per-head dim == L
#define MM (BB*LL)   // 4096

// ---------------- scratch (device globals: allocation-free) ----------------
__device__ __align__(16) __half g_xnb[MM*DD];        // ln1 out fp16
__device__ __align__(16) __half g_xn2[MM*DD];        // ln2 out fp16
__device__ __align__(16) __half g_q  [HH*MM*AA];     // q  [h][m][a]
__device__ __align__(16) __half g_kTq[HH*AA*MM];     // kT quad-packed
__device__ __align__(16) __half g_vT [HH*AA*MM];     // vT plain [h][a][m]
__device__ __align__(16) float  g_s  [HH*BB*LL*LL];  // scores fp32
__device__ __align__(16) __half g_att[MM*DD];        // attention concat fp16
__device__ __align__(16) float  g_x1 [MM*DD];        // residual fp32
__device__ __align__(16) __half g_h  [MM*FF];        // MLP hidden fp16
// prepped weights (fp16, quad-packed along K)
__device__ __align__(16) __half g_wqkv[3*HH*DD*AA];
__device__ __align__(16) __half g_wfc [DD*DD];
__device__ __align__(16) __half g_w1  [DD*FF];
__device__ __align__(16) __half g_w2  [FF*DD];

// ---------------- helpers ----------------
__device__ __forceinline__ uint32_t pack_hf(float lo, float hi) {
    __half2 h = __floats2half2_rn(lo, hi);
    return *(uint32_t*)&h;
}
__device__ __forceinline__ float gelu_exact(float x) {
    return 0.5f * x * (1.0f + erff(x * 0.7071067811865475f));
}
__device__ __forceinline__ uint32_t sptr(const void* p) {
    return (uint32_t)__cvta_generic_to_shared(p);
}
__device__ __forceinline__ void cp16(void* dst, const void* src) {
    asm volatile("cp.async.cg.shared.global [%0], [%1], 16;" :: "r"(sptr(dst)), "l"(src));
}
__device__ __forceinline__ void cp_commit() {
    asm volatile("cp.async.commit_group;");
}
template<int N>
__device__ __forceinline__ void cp_wait() {
    asm volatile("cp.async.wait_group %0;" :: "n"(N));
}
__device__ __forceinline__ void ldsm4(uint32_t* r, uint32_t addr) {
    asm volatile("ldmatrix.sync.aligned.m8n8.x4.shared.b16 {%0,%1,%2,%3}, [%4];"
                 : "=r"(r[0]), "=r"(r[1]), "=r"(r[2]), "=r"(r[3]) : "r"(addr));
}

// ---------------- quad-pack layout ----------------
// B[k][n] stored so that for quad base p (pair index, p%8<4), words
// (p, n) and (p+4, n) are adjacent 8 bytes:
// word32(k=2p,2p+1 @ n) at index (p>>3)*(8N) + (p&3)*(2N) + n*2 + ((p>>2)&1)

__device__ __forceinline__ void pack_one(const float* __restrict__ in,
                                         __half* __restrict__ out,
                                         long long pairidx, int nl)
{
    long long N = 1LL << nl;
    long long p = pairidx >> nl;
    long long n = pairidx & (N - 1);
    float v0 = in[(2 * p) * N + n];
    float v1 = in[(2 * p + 1) * N + n];
    long long w = (p >> 3) * (8 * N) + (p & 3) * (2 * N) + n * 2 + ((p >> 2) & 1);
    *(uint32_t*)(out + 2 * w) = pack_hf(v0, v1);
}

#define QP  ((long long)HH*DD*AA/2)
#define FCP ((long long)DD*DD/2)
#define W1P ((long long)DD/2*FF)
#define W2P ((long long)FF/2*DD)
#define PREP_PAIRS (3*QP + FCP + W1P + W2P)

__global__ void prep_weights(const float* __restrict__ Wq, const float* __restrict__ Wk,
                             const float* __restrict__ Wv, const float* __restrict__ Wfc,
                             const float* __restrict__ W1, const float* __restrict__ W2,
                             __half* __restrict__ wqkv, __half* __restrict__ wfc,
                             __half* __restrict__ w1, __half* __restrict__ w2)
{
    long long i = (long long)blockIdx.x * blockDim.x + threadIdx.x;
    if (i < 3 * QP) {
        int w = (int)(i / QP);
        long long r = i - (long long)w * QP;
        const float* src = (w == 0) ? Wq : (w == 1) ? Wk : Wv;
        pack_one(src, wqkv + (long long)w * (2 * QP), r, 9);
    } else if (i < 3 * QP + FCP) {
        pack_one(Wfc, wfc, i - 3 * QP, 12);
    } else if (i < 3 * QP + FCP + W1P) {
        pack_one(W1, w1, i - (3 * QP + FCP), 14);
    } else {
        pack_one(W2, w2, i - (3 * QP + FCP + W1P), 12);
    }
}

// ---------------- layernorm (fp16 output) ----------------
__global__ void ln_kernel(const float* __restrict__ x,
                          const float* __restrict__ g,
                          const float* __restrict__ b,
                          __half* __restrict__ outb)
{
    int row = blockIdx.x;
    const float4* xr = (const float4*)(x + (size_t)row * DD);
    __shared__ float red[256];
    float4 vals[4];
    float s = 0.f;
#pragma unroll
    for (int it = 0; it < 4; ++it) {
        float4 v = xr[threadIdx.x + it * 256];
        vals[it] = v;
        s += v.x + v.y + v.z + v.w;
    }
    red[threadIdx.x] = s; __syncthreads();
    for (int st = 128; st > 0; st >>= 1) {
        if (threadIdx.x < st) red[threadIdx.x] += red[threadIdx.x + st];
        __syncthreads();
    }
    float mean = red[0] * (1.f / DD);
    __syncthreads();
    float vs = 0.f;
#pragma unroll
    for (int it = 0; it < 4; ++it) {
        float4 v = vals[it];
        float dx = v.x - mean, dy = v.y - mean, dz = v.z - mean, dw = v.w - mean;
        vs += dx*dx + dy*dy + dz*dz + dw*dw;
    }
    red[threadIdx.x] = vs; __syncthreads();
    for (int st = 128; st > 0; st >>= 1) {
        if (threadIdx.x < st) red[threadIdx.x] += red[threadIdx.x + st];
        __syncthreads();
    }
    float rstd = rsqrtf(red[0] * (1.f / DD) + 1e-5f);
#pragma unroll
    for (int it = 0; it < 4; ++it) {
        int c = (threadIdx.x + it * 256) * 4;
        float4 v = vals[it];
        float4 gg = *(const float4*)(g + c);
        float4 bb = *(const float4*)(b + c);
        float rx = (v.x - mean) * rstd * gg.x + bb.x;
        float ry = (v.y - mean) * rstd * gg.y + bb.y;
        float rz = (v.z - mean) * rstd * gg.z + bb.z;
        float rw = (v.w - mean) * rstd * gg.w + bb.w;
        uint32_t* o = (uint32_t*)(outb + (size_t)row * DD);
        o[(threadIdx.x + it * 256) * 2 + 0] = pack_hf(rx, ry);
        o[(threadIdx.x + it * 256) * 2 + 1] = pack_hf(rz, rw);
    }
}

// =====================================================================
// fp16 GEMM (m16n8k16, fp32 accum): C = A[M,K] @ B (B quad-packed)
// 128x128x64 CTA tile, 128 threads, 4 warps of 64x64, 3-stage cp.async.
// A fragments via ldmatrix.x4; B fragments via LDS.64 (quad layout).
// EPI: 0 raw fp32, 1 plain fp16, 2 quad-transposed fp16 (kT),
//      3 plain-transposed fp16 (vT), 4 bias+residual fp32, 5 bias+gelu fp16
// =====================================================================
#define BA_STRIDE 144              // bytes per A row (128 data + 16 pad)
#define BQ_STRIDE 1088             // bytes per B qrow (1024 data + 64 pad)
#define BA_TILE (128 * BA_STRIDE)  // 18432
#define BQ_TILE (16 * BQ_STRIDE)   // 17408
#define BSTAGE (BA_TILE + BQ_TILE) // 35840
#define HF_SMEM (3 * BSTAGE)       // 107520

template<int EPI>
__global__ void __launch_bounds__(128, 2)
gemm_hf(const __half* __restrict__ A, const __half* __restrict__ Bq,
        float* __restrict__ Cf, __half* __restrict__ Cb,
        const float* __restrict__ bias, const float* __restrict__ res,
        int M, int N, int K, int ldq, int zdiv,
        long long sA, long long sB, long long sB2, long long sC)
{
    extern __shared__ char smem[];

    int z = blockIdx.z;
    A  += (long long)z * sA;
    Bq += (long long)(z / zdiv) * sB + (long long)(z % zdiv) * sB2;
    long long co = (long long)z * sC;

    int m0 = blockIdx.y * 128, n0 = blockIdx.x * 128;
    int tid = threadIdx.x;
    int warp = tid >> 5, lane = tid & 31;
    int wm = (warp >> 1) * 64, wn = (warp & 1) * 64;
    int gid = lane >> 2, tig = lane & 3;
    uint32_t a_lane_off = (uint32_t)((lane & 15) * BA_STRIDE + (lane >> 4) * 16);

    float acc[4][8][4];
#pragma unroll
    for (int a = 0; a < 4; ++a)
#pragma unroll
        for (int b = 0; b < 8; ++b)
#pragma unroll
            for (int c = 0; c < 4; ++c) acc[a][b][c] = 0.f;

    const int T = K >> 6;

    auto load_tile = [&](int t, int st) {
        char* As = smem + st * BSTAGE;
        char* Bs = As + BA_TILE;
#pragma unroll
        for (int i = 0; i < 8; ++i) {          // A: 128 rows x 8 chunks of 16B
            int idx = tid + i * 128;
            int r = idx >> 3, c = idx & 7;
            cp16(As + r * BA_STRIDE + c * 16,
                 A + (size_t)(m0 + r) * K + t * 64 + c * 8);
        }
#pragma unroll
        for (int i = 0; i < 8; ++i) {          // B: 16 qrows x 64 chunks of 16B
            int idx = tid + i * 128;
            int qr = idx >> 6, ch = idx & 63;
            cp16(Bs + qr * BQ_STRIDE + ch * 16,
                 Bq + (size_t)(t * 16 + qr) * ldq + (size_t)n0 * 4 + ch * 8);
        }
    };

    load_tile(0, 0);
    cp_commit();
    if (T > 1) load_tile(1, 1);
    cp_commit();

    int st = 0;
    for (int t = 0; t < T; ++t) {
        cp_wait<1>();
        __syncthreads();
        int st2 = st + 2; if (st2 >= 3) st2 -= 3;
        if (t + 2 < T) load_tile(t + 2, st2);
        cp_commit();

        const char* As = smem + st * BSTAGE;
        const char* Bs = As + BA_TILE;
        uint32_t As_addr = sptr(As) + wm * BA_STRIDE + a_lane_off;

#pragma unroll
        for (int ksg = 0; ksg < 4; ++ksg) {
            uint32_t af[4][4];
#pragma unroll
            for (int mf = 0; mf < 4; ++mf)
                ldsm4(af[mf], As_addr + mf * 16 * BA_STRIDE + ksg * 32);
            const char* brow = Bs + (ksg * 4 + tig) * BQ_STRIDE + (wn + gid) * 8;
#pragma unroll
            for (int nf = 0; nf < 8; ++nf) {
                uint2 bb = *(const uint2*)(brow + nf * 64);
#pragma unroll
                for (int mf = 0; mf < 4; ++mf) {
                    asm volatile(
                        "mma.sync.aligned.m16n8k16.row.col.f32.f16.f16.f32 "
                        "{%0,%1,%2,%3}, {%4,%5,%6,%7}, {%8,%9}, {%0,%1,%2,%3};"
                        : "+f"(acc[mf][nf][0]), "+f"(acc[mf][nf][1]),
                          "+f"(acc[mf][nf][2]), "+f"(acc[mf][nf][3])
                        : "r"(af[mf][0]), "r"(af[mf][1]), "r"(af[mf][2]), "r"(af[mf][3]),
                          "r"(bb.x), "r"(bb.y));
                }
            }
        }
        if (++st >= 3) st = 0;
    }

    // ---- epilogue ----
    float* CF = Cf + co;
    __half* CB = Cb + co;
#pragma unroll
    for (int mf = 0; mf < 4; ++mf) {
        int r0 = m0 + wm + mf * 16 + gid;
#pragma unroll
        for (int nf = 0; nf < 8; ++nf) {
            int c = n0 + wn + nf * 8 + tig * 2;
#pragma unroll
            for (int half = 0; half < 2; ++half) {
                int r = r0 + half * 8;
                float v0 = acc[mf][nf][half * 2 + 0];
                float v1 = acc[mf][nf][half * 2 + 1];
                if (EPI == 0) {
                    *(float2*)(CF + (size_t)r * N + c) = make_float2(v0, v1);
                } else if (EPI == 1) {
                    *(uint32_t*)(CB + (size_t)r * N + c) = pack_hf(v0, v1);
                } else if (EPI == 2) {
                    // quad-pack: output k-dim = c, n-dim = r, width M
                    size_t w = (size_t)(c >> 4) * (8 * (size_t)M)
                             + (size_t)((c >> 1) & 3) * (2 * (size_t)M)
                             + (size_t)r * 2 + ((c >> 3) & 1);
                    *(uint32_t*)(CB + 2 * w) = pack_hf(v0, v1);
                } else if (EPI == 3) {
                    CB[(size_t)c * M + r]       = __float2half(v0);
                    CB[(size_t)(c + 1) * M + r] = __float2half(v1);
                } else if (EPI == 4) {
                    v0 += bias[c]; v1 += bias[c + 1];
                    size_t off = (size_t)r * N + c;
                    v0 += res[off]; v1 += res[off + 1];
                    *(float2*)(CF + off) = make_float2(v0, v1);
                } else {   // 5: bias + gelu -> fp16
                    v0 = gelu_exact(v0 + bias[c]);
                    v1 = gelu_exact(v1 + bias[c + 1]);
                    *(uint32_t*)(CB + (size_t)r * N + c) = pack_hf(v0, v1);
                }
            }
        }
    }
}

// ---------------- column softmax + p * v^T + head concat -> att (fp16) ----------------
__global__ void softmax_att_kernel(const float* __restrict__ s,
                                   const __half* __restrict__ vT,
                                   __half* __restrict__ att)
{
    int z = blockIdx.y;          // z = h*B + b
    int h = z >> 3, b = z & 7;
    int j0 = blockIdx.x * 32;
    int tx = threadIdx.x, ty = threadIdx.y;   // 32 x 16
    const float* sp = s + (size_t)z * LL * LL;
    const float rs = 0.04419417382415922f;    // 1/sqrt(512)
    int j = j0 + tx;

    float part = 0.f;
    for (int it = 0; it < 32; ++it) {
        int i = it * 16 + ty;
        float val = (j <= i) ? sp[(size_t)i * LL + j] : -1000.f;
        part += expf(val * rs);
    }
    __shared__ float red[16][32];
    __shared__ float cinv[32];
    red[ty][tx] = part; __syncthreads();
    if (ty < 8) red[ty][tx] += red[ty + 8][tx];
    __syncthreads();
    if (ty < 4) red[ty][tx] += red[ty + 4][tx];
    __syncthreads();
    if (ty < 2) red[ty][tx] += red[ty + 2][tx];
    __syncthreads();
    if (ty == 0) cinv[tx] = 1.f / (red[0][tx] + red[1][tx]);
    __syncthreads();
    float ci = cinv[tx];

    const __half* vrow = vT + (size_t)h * AA * MM + (size_t)b * LL + j;
    size_t attb = (size_t)b * LL * DD + (size_t)h * AA + j;
    for (int it = 0; it < 32; ++it) {
        int i = it * 16 + ty;
        float val = (j <= i) ? sp[(size_t)i * LL + j] : -1000.f;
        float p = expf(val * rs) * ci;
        float vv = __half2float(vrow[(size_t)i * MM]);
        att[attb + (size_t)i * DD] = __float2half(p * vv);
    }
}

// ---------------- launch ----------------
extern "C" void kernel_launch(void* const* d_in, const int* in_sizes, int n_in,
                              void* d_out, int out_size)
{
    (void)in_sizes; (void)n_in; (void)out_size;
    const float* x    = (const float*)d_in[0];
    const float* Wq   = (const float*)d_in[2];
    const float* Wk   = (const float*)d_in[3];
    const float* Wv   = (const float*)d_in[4];
    const float* fc_w = (const float*)d_in[5];
    const float* fc_b = (const float*)d_in[6];
    const float* ln1g = (const float*)d_in[7];
    const float* ln1b = (const float*)d_in[8];
    const float* W1   = (const float*)d_in[9];
    const float* b1   = (const float*)d_in[10];
    const float* W2   = (const float*)d_in[11];
    const float* b2   = (const float*)d_in[12];
    const float* ln2g = (const float*)d_in[13];
    const float* ln2b = (const float*)d_in[14];
    float* out = (float*)d_out;

    float *s, *x1;
    __half *xnb, *xn2, *q, *kTq, *vT, *att, *hb, *wqkv, *wfc, *w1, *w2;
    cudaGetSymbolAddress((void**)&xnb,  g_xnb);
    cudaGetSymbolAddress((void**)&xn2,  g_xn2);
    cudaGetSymbolAddress((void**)&q,    g_q);
    cudaGetSymbolAddress((void**)&kTq,  g_kTq);
    cudaGetSymbolAddress((void**)&vT,   g_vT);
    cudaGetSymbolAddress((void**)&s,    g_s);
    cudaGetSymbolAddress((void**)&att,  g_att);
    cudaGetSymbolAddress((void**)&x1,   g_x1);
    cudaGetSymbolAddress((void**)&hb,   g_h);
    cudaGetSymbolAddress((void**)&wqkv, g_wqkv);
    cudaGetSymbolAddress((void**)&wfc,  g_wfc);
    cudaGetSymbolAddress((void**)&w1,   g_w1);
    cudaGetSymbolAddress((void**)&w2,   g_w2);

    cudaFuncSetAttribute(gemm_hf<0>, cudaFuncAttributeMaxDynamicSharedMemorySize, HF_SMEM);
    cudaFuncSetAttribute(gemm_hf<1>, cudaFuncAttributeMaxDynamicSharedMemorySize, HF_SMEM);
    cudaFuncSetAttribute(gemm_hf<2>, cudaFuncAttributeMaxDynamicSharedMemorySize, HF_SMEM);
    cudaFuncSetAttribute(gemm_hf<3>, cudaFuncAttributeMaxDynamicSharedMemorySize, HF_SMEM);
    cudaFuncSetAttribute(gemm_hf<4>, cudaFuncAttributeMaxDynamicSharedMemorySize, HF_SMEM);
    cudaFuncSetAttribute(gemm_hf<5>, cudaFuncAttributeMaxDynamicSharedMemorySize, HF_SMEM);

    const long long HDA = (long long)HH * DD * AA;
    const long long HAM = (long long)AA * MM;

    // launch 0: ln1
    ln_kernel<<<MM, 256>>>(x, ln1g, ln1b, xnb);

    // launch 1: fused weight prep (fp16 quad-pack, all weights)
    prep_weights<<<(unsigned)(PREP_PAIRS / 256), 256>>>(
        Wq, Wk, Wv, fc_w, W1, W2, wqkv, wfc, w1, w2);

    // launches 2-4: QKV (z = head)
    {
        dim3 grid(AA / 128, MM / 128, HH);
        gemm_hf<1><<<grid, 128, HF_SMEM>>>(xnb, wqkv + 0 * HDA, nullptr, q,
                                           nullptr, nullptr,
                                           MM, AA, DD, 4 * AA, 1,
                                           0, (long long)DD * AA, 0, (long long)MM * AA);
        gemm_hf<2><<<grid, 128, HF_SMEM>>>(xnb, wqkv + 1 * HDA, nullptr, kTq,
                                           nullptr, nullptr,
                                           MM, AA, DD, 4 * AA, 1,
                                           0, (long long)DD * AA, 0, HAM);
        gemm_hf<3><<<grid, 128, HF_SMEM>>>(xnb, wqkv + 2 * HDA, nullptr, vT,
                                           nullptr, nullptr,
                                           MM, AA, DD, 4 * AA, 1,
                                           0, (long long)DD * AA, 0, HAM);
    }

    // launch 5 (ncu target): S = q @ k^T (64 batches, z = h*8 + b)
    {
        dim3 grid(LL / 128, LL / 128, HH * BB);
        gemm_hf<0><<<grid, 128, HF_SMEM>>>(q, kTq, s, nullptr,
                                           nullptr, nullptr,
                                           LL, LL, AA, 4 * MM, 8,
                                           (long long)LL * AA, HAM, 4LL * LL,
                                           (long long)LL * LL);
    }

    // launch 6: column softmax + p*v^T + concat
    {
        dim3 grid(LL / 32, HH * BB);
        dim3 blk(32, 16);
        softmax_att_kernel<<<grid, blk>>>(s, vT, att);
    }

    // launch 7: x1 = x + att @ fc_w + fc_b
    {
        dim3 grid(DD / 128, MM / 128, 1);
        gemm_hf<4><<<grid, 128, HF_SMEM>>>(att, wfc, x1, nullptr,
                                           fc_b, x,
                                           MM, DD, DD, 4 * DD, 1,
                                           0, 0, 0, 0);
    }

    // launch 8: ln2
    ln_kernel<<<MM, 256>>>(x1, ln2g, ln2b, xn2);

    // launch 9: h = gelu(xn2 @ W1 + b1) -> fp16
    {
        dim3 grid(FF / 128, MM / 128, 1);
        gemm_hf<5><<<grid, 128, HF_SMEM>>>(xn2, w1, nullptr, hb,
                                           b1, nullptr,
                                           MM, FF, DD, 4 * FF, 1,
                                           0, 0, 0, 0);
    }

    // launch 10: out = x1 + h @ W2 + b2
    {
        dim3 grid(DD / 128, MM / 128, 1);
        gemm_hf<4><<<grid, 128, HF_SMEM>>>(hb, w2, out, nullptr,
                                           b2, x1,
                                           MM, DD, FF, 4 * DD, 1,
                                           0, 0, 0, 0);
    }
}

// round 10
// speedup vs baseline: 2.9126x; 1.0511x over previous
#include <cuda_runtime.h>
#include <cuda_fp16.h>
#include <cstdint>
#include <math.h>

#define BB 8
#define LL 512
#define DD 4096
#define HH 8
#define FF 16384
#define AA 512       // per-head dim == L
#define MM (BB*LL)   // 4096

// ---------------- scratch (device globals: allocation-free) ----------------
__device__ __align__(16) __half g_xnb[MM*DD];        // ln1 out fp16
__device__ __align__(16) __half g_xn2[MM*DD];        // ln2 out fp16
__device__ __align__(16) __half g_q  [HH*MM*AA];     // q  [h][m][a]
__device__ __align__(16) __half g_kTq[HH*AA*MM];     // kT quad-packed
__device__ __align__(16) __half g_vT [HH*AA*MM];     // vT plain [h][a][m]
__device__ __align__(16) float  g_s  [HH*BB*LL*LL];  // scores fp32
__device__ __align__(16) __half g_att[MM*DD];        // attention concat fp16
__device__ __align__(16) float  g_x1 [MM*DD];        // residual fp32
__device__ __align__(16) __half g_h  [MM*FF];        // MLP hidden fp16
// prepped weights (fp16, quad-packed along K)
__device__ __align__(16) __half g_wqkv[3*HH*DD*AA];
__device__ __align__(16) __half g_wfc [DD*DD];
__device__ __align__(16) __half g_w1  [DD*FF];
__device__ __align__(16) __half g_w2  [FF*DD];

// ---------------- helpers ----------------
__device__ __forceinline__ uint32_t pack_hf(float lo, float hi) {
    __half2 h = __floats2half2_rn(lo, hi);
    return *(uint32_t*)&h;
}
__device__ __forceinline__ float gelu_exact(float x) {
    return 0.5f * x * (1.0f + erff(x * 0.7071067811865475f));
}
__device__ __forceinline__ uint32_t sptr(const void* p) {
    return (uint32_t)__cvta_generic_to_shared(p);
}
__device__ __forceinline__ void cp16(void* dst, const void* src) {
    asm volatile("cp.async.cg.shared.global [%0], [%1], 16;" :: "r"(sptr(dst)), "l"(src));
}
__device__ __forceinline__ void cp_commit() {
    asm volatile("cp.async.commit_group;");
}
template<int N>
__device__ __forceinline__ void cp_wait() {
    asm volatile("cp.async.wait_group %0;" :: "n"(N));
}

// ---------------- quad-pack layout ----------------
// B[k][n]: word32(k=2p,2p+1 @ n) at (p>>3)*(8N) + (p&3)*(2N) + n*2 + ((p>>2)&1)
__device__ __forceinline__ void pack_one(const float* __restrict__ in,
                                         __half* __restrict__ out,
                                         long long pairidx, int nl)
{
    long long N = 1LL << nl;
    long long p = pairidx >> nl;
    long long n = pairidx & (N - 1);
    float v0 = in[(2 * p) * N + n];
    float v1 = in[(2 * p + 1) * N + n];
    long long w = (p >> 3) * (8 * N) + (p & 3) * (2 * N) + n * 2 + ((p >> 2) & 1);
    *(uint32_t*)(out + 2 * w) = pack_hf(v0, v1);
}

#define QP  ((long long)HH*DD*AA/2)
#define FCP ((long long)DD*DD/2)
#define W1P ((long long)DD/2*FF)
#define W2P ((long long)FF/2*DD)
#define PREP_PAIRS (3*QP + FCP + W1P + W2P)

__global__ void prep_weights(const float* __restrict__ Wq, const float* __restrict__ Wk,
                             const float* __restrict__ Wv, const float* __restrict__ Wfc,
                             const float* __restrict__ W1, const float* __restrict__ W2,
                             __half* __restrict__ wqkv, __half* __restrict__ wfc,
                             __half* __restrict__ w1, __half* __restrict__ w2)
{
    long long i = (long long)blockIdx.x * blockDim.x + threadIdx.x;
    if (i < 3 * QP) {
        int w = (int)(i / QP);
        long long r = i - (long long)w * QP;
        const float* src = (w == 0) ? Wq : (w == 1) ? Wk : Wv;
        pack_one(src, wqkv + (long long)w * (2 * QP), r, 9);
    } else if (i < 3 * QP + FCP) {
        pack_one(Wfc, wfc, i - 3 * QP, 12);
    } else if (i < 3 * QP + FCP + W1P) {
        pack_one(W1, w1, i - (3 * QP + FCP), 14);
    } else {
        pack_one(W2, w2, i - (3 * QP + FCP + W1P), 12);
    }
}

// ---------------- layernorm (fp16 output) ----------------
__global__ void ln_kernel(const float* __restrict__ x,
                          const float* __restrict__ g,
                          const float* __restrict__ b,
                          __half* __restrict__ outb)
{
    int row = blockIdx.x;
    const float4* xr = (const float4*)(x + (size_t)row * DD);
    __shared__ float red[256];
    float4 vals[4];
    float s = 0.f;
#pragma unroll
    for (int it = 0; it < 4; ++it) {
        float4 v = xr[threadIdx.x + it * 256];
        vals[it] = v;
        s += v.x + v.y + v.z + v.w;
    }
    red[threadIdx.x] = s; __syncthreads();
    for (int st = 128; st > 0; st >>= 1) {
        if (threadIdx.x < st) red[threadIdx.x] += red[threadIdx.x + st];
        __syncthreads();
    }
    float mean = red[0] * (1.f / DD);
    __syncthreads();
    float vs = 0.f;
#pragma unroll
    for (int it = 0; it < 4; ++it) {
        float4 v = vals[it];
        float dx = v.x - mean, dy = v.y - mean, dz = v.z - mean, dw = v.w - mean;
        vs += dx*dx + dy*dy + dz*dz + dw*dw;
    }
    red[threadIdx.x] = vs; __syncthreads();
    for (int st = 128; st > 0; st >>= 1) {
        if (threadIdx.x < st) red[threadIdx.x] += red[threadIdx.x + st];
        __syncthreads();
    }
    float rstd = rsqrtf(red[0] * (1.f / DD) + 1e-5f);
#pragma unroll
    for (int it = 0; it < 4; ++it) {
        int c = (threadIdx.x + it * 256) * 4;
        float4 v = vals[it];
        float4 gg = *(const float4*)(g + c);
        float4 bb = *(const float4*)(b + c);
        float rx = (v.x - mean) * rstd * gg.x + bb.x;
        float ry = (v.y - mean) * rstd * gg.y + bb.y;
        float rz = (v.z - mean) * rstd * gg.z + bb.z;
        float rw = (v.w - mean) * rstd * gg.w + bb.w;
        uint32_t* o = (uint32_t*)(outb + (size_t)row * DD);
        o[(threadIdx.x + it * 256) * 2 + 0] = pack_hf(rx, ry);
        o[(threadIdx.x + it * 256) * 2 + 1] = pack_hf(rz, rw);
    }
}

// =====================================================================
// fp16 GEMM (m16n8k16, fp32 accum): C = A[M,K] @ B (B quad-packed)
// 128x128x64 CTA tile, 128 threads, 4 warps of 64x64, 3-stage cp.async.
// A fragments via LDS.32 (high MLP); B fragments via LDS.64 (quad layout).
// EPI: 0 raw fp32, 1 plain fp16, 2 quad-transposed fp16 (kT),
//      3 plain-transposed fp16 (vT), 4 bias+residual fp32, 5 bias+gelu fp16,
//      6 merged QKV (dispatch on z>>3: 0->plain, 1->quadT, 2->plainT)
// =====================================================================
#define BA_STRIDE 144              // bytes per A row (128 data + 16 pad)
#define BQ_STRIDE 1088             // bytes per B qrow (1024 data + 64 pad)
#define BA_TILE (128 * BA_STRIDE)  // 18432
#define BQ_TILE (16 * BQ_STRIDE)   // 17408
#define BSTAGE (BA_TILE + BQ_TILE) // 35840
#define HF_SMEM (3 * BSTAGE)       // 107520

template<int EPI>
__global__ void __launch_bounds__(128, 2)
gemm_hf(const __half* __restrict__ A, const __half* __restrict__ Bq,
        float* __restrict__ Cf, __half* __restrict__ Cb,
        __half* __restrict__ Cb2, __half* __restrict__ Cb3,
        const float* __restrict__ bias, const float* __restrict__ res,
        int M, int N, int K, int ldq, int zdiv,
        long long sA, long long sB, long long sB2, long long sC)
{
    extern __shared__ char smem[];

    int z = blockIdx.z;
    A  += (long long)z * sA;
    Bq += (long long)(z / zdiv) * sB + (long long)(z % zdiv) * sB2;
    long long co = (EPI == 6) ? (long long)(z & 7) * sC : (long long)z * sC;
    int which = z >> 3;   // used only by EPI 6

    int m0 = blockIdx.y * 128, n0 = blockIdx.x * 128;
    int tid = threadIdx.x;
    int warp = tid >> 5, lane = tid & 31;
    int wm = (warp >> 1) * 64, wn = (warp & 1) * 64;
    int gid = lane >> 2, tig = lane & 3;

    float acc[4][8][4];
#pragma unroll
    for (int a = 0; a < 4; ++a)
#pragma unroll
        for (int b = 0; b < 8; ++b)
#pragma unroll
            for (int c = 0; c < 4; ++c) acc[a][b][c] = 0.f;

    const int T = K >> 6;

    auto load_tile = [&](int t, int st) {
        char* As = smem + st * BSTAGE;
        char* Bs = As + BA_TILE;
#pragma unroll
        for (int i = 0; i < 8; ++i) {          // A: 128 rows x 8 chunks of 16B
            int idx = tid + i * 128;
            int r = idx >> 3, c = idx & 7;
            cp16(As + r * BA_STRIDE + c * 16,
                 A + (size_t)(m0 + r) * K + t * 64 + c * 8);
        }
#pragma unroll
        for (int i = 0; i < 8; ++i) {          // B: 16 qrows x 64 chunks of 16B
            int idx = tid + i * 128;
            int qr = idx >> 6, ch = idx & 63;
            cp16(Bs + qr * BQ_STRIDE + ch * 16,
                 Bq + (size_t)(t * 16 + qr) * ldq + (size_t)n0 * 4 + ch * 8);
        }
    };

    load_tile(0, 0);
    cp_commit();
    if (T > 1) load_tile(1, 1);
    cp_commit();

    int st = 0;
    for (int t = 0; t < T; ++t) {
        cp_wait<1>();
        __syncthreads();
        int st2 = st + 2; if (st2 >= 3) st2 -= 3;
        if (t + 2 < T) load_tile(t + 2, st2);
        cp_commit();

        const char* As = smem + st * BSTAGE;
        const char* Bs = As + BA_TILE;

#pragma unroll
        for (int ksg = 0; ksg < 4; ++ksg) {
            uint32_t af[4][4];
#pragma unroll
            for (int mf = 0; mf < 4; ++mf) {
                const char* base = As + (wm + mf * 16 + gid) * BA_STRIDE + ksg * 32 + tig * 4;
                af[mf][0] = *(const uint32_t*)(base);
                af[mf][1] = *(const uint32_t*)(base + 8 * BA_STRIDE);
                af[mf][2] = *(const uint32_t*)(base + 16);
                af[mf][3] = *(const uint32_t*)(base + 8 * BA_STRIDE + 16);
            }
            const char* brow = Bs + (ksg * 4 + tig) * BQ_STRIDE + (wn + gid) * 8;
#pragma unroll
            for (int nf = 0; nf < 8; ++nf) {
                uint2 bb = *(const uint2*)(brow + nf * 64);
#pragma unroll
                for (int mf = 0; mf < 4; ++mf) {
                    asm volatile(
                        "mma.sync.aligned.m16n8k16.row.col.f32.f16.f16.f32 "
                        "{%0,%1,%2,%3}, {%4,%5,%6,%7}, {%8,%9}, {%0,%1,%2,%3};"
                        : "+f"(acc[mf][nf][0]), "+f"(acc[mf][nf][1]),
                          "+f"(acc[mf][nf][2]), "+f"(acc[mf][nf][3])
                        : "r"(af[mf][0]), "r"(af[mf][1]), "r"(af[mf][2]), "r"(af[mf][3]),
                          "r"(bb.x), "r"(bb.y));
                }
            }
        }
        if (++st >= 3) st = 0;
    }

    // ---- epilogue ----
    float* CF = Cf + co;
#pragma unroll
    for (int mf = 0; mf < 4; ++mf) {
        int r0 = m0 + wm + mf * 16 + gid;
#pragma unroll
        for (int nf = 0; nf < 8; ++nf) {
            int c = n0 + wn + nf * 8 + tig * 2;
#pragma unroll
            for (int half = 0; half < 2; ++half) {
                int r = r0 + half * 8;
                float v0 = acc[mf][nf][half * 2 + 0];
                float v1 = acc[mf][nf][half * 2 + 1];
                if (EPI == 0) {
                    *(float2*)(CF + (size_t)r * N + c) = make_float2(v0, v1);
                } else if (EPI == 4) {
                    v0 += bias[c]; v1 += bias[c + 1];
                    size_t off = (size_t)r * N + c;
                    v0 += res[off]; v1 += res[off + 1];
                    *(float2*)(CF + off) = make_float2(v0, v1);
                } else if (EPI == 5) {   // bias + gelu -> fp16
                    v0 = gelu_exact(v0 + bias[c]);
                    v1 = gelu_exact(v1 + bias[c + 1]);
                    *(uint32_t*)(Cb + co + (size_t)r * N + c) = pack_hf(v0, v1);
                } else if (EPI == 6) {
                    if (which == 0) {          // q: plain fp16 [m][a]
                        *(uint32_t*)(Cb + co + (size_t)r * N + c) = pack_hf(v0, v1);
                    } else if (which == 1) {   // kT: quad-packed, k-dim=c, n-dim=r
                        size_t w = (size_t)(c >> 4) * (8 * (size_t)M)
                                 + (size_t)((c >> 1) & 3) * (2 * (size_t)M)
                                 + (size_t)r * 2 + ((c >> 3) & 1);
                        *(uint32_t*)(Cb2 + co + 2 * w) = pack_hf(v0, v1);
                    } else {                   // vT: plain transposed
                        Cb3[co + (size_t)c * M + r]       = __float2half(v0);
                        Cb3[co + (size_t)(c + 1) * M + r] = __float2half(v1);
                    }
                }
            }
        }
    }
}

// ---------------- column softmax + p * v^T + head concat -> att (fp16) ----------------
__global__ void softmax_att_kernel(const float* __restrict__ s,
                                   const __half* __restrict__ vT,
                                   __half* __restrict__ att)
{
    int z = blockIdx.y;          // z = h*B + b
    int h = z >> 3, b = z & 7;
    int j0 = blockIdx.x * 32;
    int tx = threadIdx.x, ty = threadIdx.y;   // 32 x 16
    const float* sp = s + (size_t)z * LL * LL;
    const float rs = 0.04419417382415922f;    // 1/sqrt(512)
    int j = j0 + tx;

    float part = 0.f;
    for (int it = 0; it < 32; ++it) {
        int i = it * 16 + ty;
        float val = (j <= i) ? sp[(size_t)i * LL + j] : -1000.f;
        part += expf(val * rs);
    }
    __shared__ float red[16][32];
    __shared__ float cinv[32];
    red[ty][tx] = part; __syncthreads();
    if (ty < 8) red[ty][tx] += red[ty + 8][tx];
    __syncthreads();
    if (ty < 4) red[ty][tx] += red[ty + 4][tx];
    __syncthreads();
    if (ty < 2) red[ty][tx] += red[ty + 2][tx];
    __syncthreads();
    if (ty == 0) cinv[tx] = 1.f / (red[0][tx] + red[1][tx]);
    __syncthreads();
    float ci = cinv[tx];

    const __half* vrow = vT + (size_t)h * AA * MM + (size_t)b * LL + j;
    size_t attb = (size_t)b * LL * DD + (size_t)h * AA + j;
    for (int it = 0; it < 32; ++it) {
        int i = it * 16 + ty;
        float val = (j <= i) ? sp[(size_t)i * LL + j] : -1000.f;
        float p = expf(val * rs) * ci;
        float vv = __half2float(vrow[(size_t)i * MM]);
        att[attb + (size_t)i * DD] = __float2half(p * vv);
    }
}

// ---------------- launch ----------------
extern "C" void kernel_launch(void* const* d_in, const int* in_sizes, int n_in,
                              void* d_out, int out_size)
{
    (void)in_sizes; (void)n_in; (void)out_size;
    const float* x    = (const float*)d_in[0];
    const float* Wq   = (const float*)d_in[2];
    const float* Wk   = (const float*)d_in[3];
    const float* Wv   = (const float*)d_in[4];
    const float* fc_w = (const float*)d_in[5];
    const float* fc_b = (const float*)d_in[6];
    const float* ln1g = (const float*)d_in[7];
    const float* ln1b = (const float*)d_in[8];
    const float* W1   = (const float*)d_in[9];
    const float* b1   = (const float*)d_in[10];
    const float* W2   = (const float*)d_in[11];
    const float* b2   = (const float*)d_in[12];
    const float* ln2g = (const float*)d_in[13];
    const float* ln2b = (const float*)d_in[14];
    float* out = (float*)d_out;

    float *s, *x1;
    __half *xnb, *xn2, *q, *kTq, *vT, *att, *hb, *wqkv, *wfc, *w1, *w2;
    cudaGetSymbolAddress((void**)&xnb,  g_xnb);
    cudaGetSymbolAddress((void**)&xn2,  g_xn2);
    cudaGetSymbolAddress((void**)&q,    g_q);
    cudaGetSymbolAddress((void**)&kTq,  g_kTq);
    cudaGetSymbolAddress((void**)&vT,   g_vT);
    cudaGetSymbolAddress((void**)&s,    g_s);
    cudaGetSymbolAddress((void**)&att,  g_att);
    cudaGetSymbolAddress((void**)&x1,   g_x1);
    cudaGetSymbolAddress((void**)&hb,   g_h);
    cudaGetSymbolAddress((void**)&wqkv, g_wqkv);
    cudaGetSymbolAddress((void**)&wfc,  g_wfc);
    cudaGetSymbolAddress((void**)&w1,   g_w1);
    cudaGetSymbolAddress((void**)&w2,   g_w2);

    cudaFuncSetAttribute(gemm_hf<0>, cudaFuncAttributeMaxDynamicSharedMemorySize, HF_SMEM);
    cudaFuncSetAttribute(gemm_hf<4>, cudaFuncAttributeMaxDynamicSharedMemorySize, HF_SMEM);
    cudaFuncSetAttribute(gemm_hf<5>, cudaFuncAttributeMaxDynamicSharedMemorySize, HF_SMEM);
    cudaFuncSetAttribute(gemm_hf<6>, cudaFuncAttributeMaxDynamicSharedMemorySize, HF_SMEM);

    const long long HAM = (long long)AA * MM;

    // launch 0: ln1
    ln_kernel<<<MM, 256>>>(x, ln1g, ln1b, xnb);

    // launch 1: fused weight prep (fp16 quad-pack, all weights)
    prep_weights<<<(unsigned)(PREP_PAIRS / 256), 256>>>(
        Wq, Wk, Wv, fc_w, W1, W2, wqkv, wfc, w1, w2);

    // launch 2: merged QKV (z = which*8 + head, 3072 CTAs)
    {
        dim3 grid(AA / 128, MM / 128, 3 * HH);
        gemm_hf<6><<<grid, 128, HF_SMEM>>>(xnb, wqkv, nullptr, q, kTq, vT,
                                           nullptr, nullptr,
                                           MM, AA, DD, 4 * AA, 1,
                                           0, (long long)DD * AA, 0, (long long)MM * AA);
    }

    // launch 3: S = q @ k^T (64 batches, z = h*8 + b)
    {
        dim3 grid(LL / 128, LL / 128, HH * BB);
        gemm_hf<0><<<grid, 128, HF_SMEM>>>(q, kTq, s, nullptr, nullptr, nullptr,
                                           nullptr, nullptr,
                                           LL, LL, AA, 4 * MM, 8,
                                           (long long)LL * AA, HAM, 4LL * LL,
                                           (long long)LL * LL);
    }

    // launch 4: column softmax + p*v^T + concat
    {
        dim3 grid(LL / 32, HH * BB);
        dim3 blk(32, 16);
        softmax_att_kernel<<<grid, blk>>>(s, vT, att);
    }

    // launch 5 (ncu target): x1 = x + att @ fc_w + fc_b
    {
        dim3 grid(DD / 128, MM / 128, 1);
        gemm_hf<4><<<grid, 128, HF_SMEM>>>(att, wfc, x1, nullptr, nullptr, nullptr,
                                           fc_b, x,
                                           MM, DD, DD, 4 * DD, 1,
                                           0, 0, 0, 0);
    }

    // launch 6: ln2
    ln_kernel<<<MM, 256>>>(x1, ln2g, ln2b, xn2);

    // launch 7: h = gelu(xn2 @ W1 + b1) -> fp16
    {
        dim3 grid(FF / 128, MM / 128, 1);
        gemm_hf<5><<<grid, 128, HF_SMEM>>>(xn2, w1, nullptr, hb, nullptr, nullptr,
                                           b1, nullptr,
                                           MM, FF, DD, 4 * FF, 1,
                                           0, 0, 0, 0);
    }

    // launch 8: out = x1 + h @ W2 + b2
    {
        dim3 grid(DD / 128, MM / 128, 1);
        gemm_hf<4><<<grid, 128, HF_SMEM>>>(hb, w2, out, nullptr, nullptr, nullptr,
                                           b2, x1,
                                           MM, DD, FF, 4 * DD, 1,
                                           0, 0, 0, 0);
    }
}